// round 1
// baseline (speedup 1.0000x reference)
#include <cuda_runtime.h>
#include <cstdio>

#define B_  16
#define N_  512
#define M_  8
#define D_  768
#define H_  12
#define DH  64
__device__ __constant__ float kSCALE = 0.125f; // 64^{-0.5}

// ---------------- scratch (device globals; no cudaMalloc allowed) ----------------
__device__ float g_q    [B_ * N_ * D_];              // (B,N,D)        25 MB
__device__ float g_kv   [B_ * N_ * 2 * D_];          // (B,N,2D)       50 MB
__device__ float g_kvsim[B_ * N_ * M_ * 2 * D_];     // (B,N,M,2D)    403 MB
__device__ float g_att  [B_ * N_ * D_];              // (B,N,D)        25 MB

// ---------------- SGEMM + bias: C[M,N] = A[M,K] @ B[K,N] + bias[N] ----------------
// 128x128 block tile, BK=8, 256 threads, 8x8 per-thread microtile.
// Requires M%128==0, N%128==0, K%8==0 (true for all call sites).
__global__ __launch_bounds__(256) void sgemm_bias_kernel(
    const float* __restrict__ A, const float* __restrict__ Bw,
    const float* __restrict__ bias, float* __restrict__ C,
    int M, int N, int K)
{
    __shared__ float As[8][128];
    __shared__ float Bs[8][128];

    const int tid = threadIdx.x;
    const int bm = blockIdx.y * 128;
    const int bn = blockIdx.x * 128;

    const int arow = tid >> 1;          // 0..127
    const int acol = (tid & 1) << 2;    // 0 or 4
    const int brow = tid >> 5;          // 0..7
    const int bcol = (tid & 31) << 2;   // 0..124

    const int ty = (tid >> 4) << 3;     // row offset in tile
    const int tx = (tid & 15) << 3;     // col offset in tile

    float acc[8][8];
    #pragma unroll
    for (int i = 0; i < 8; i++)
        #pragma unroll
        for (int j = 0; j < 8; j++) acc[i][j] = 0.f;

    const size_t a_base = (size_t)(bm + arow) * K + acol;
    for (int k0 = 0; k0 < K; k0 += 8) {
        float4 av = *(const float4*)&A[a_base + k0];
        As[acol + 0][arow] = av.x;
        As[acol + 1][arow] = av.y;
        As[acol + 2][arow] = av.z;
        As[acol + 3][arow] = av.w;
        *(float4*)&Bs[brow][bcol] =
            *(const float4*)&Bw[(size_t)(k0 + brow) * N + bn + bcol];
        __syncthreads();

        #pragma unroll
        for (int kk = 0; kk < 8; kk++) {
            float ra[8], rb[8];
            #pragma unroll
            for (int i = 0; i < 8; i++) ra[i] = As[kk][ty + i];
            #pragma unroll
            for (int j = 0; j < 8; j++) rb[j] = Bs[kk][tx + j];
            #pragma unroll
            for (int i = 0; i < 8; i++)
                #pragma unroll
                for (int j = 0; j < 8; j++)
                    acc[i][j] += ra[i] * rb[j];
        }
        __syncthreads();
    }

    #pragma unroll
    for (int i = 0; i < 8; i++) {
        #pragma unroll
        for (int j = 0; j < 8; j += 4) {
            float4 o;
            o.x = acc[i][j + 0] + bias[bn + tx + j + 0];
            o.y = acc[i][j + 1] + bias[bn + tx + j + 1];
            o.z = acc[i][j + 2] + bias[bn + tx + j + 2];
            o.w = acc[i][j + 3] + bias[bn + tx + j + 3];
            *(float4*)&C[(size_t)(bm + ty + i) * N + bn + tx + j] = o;
        }
    }
}

// ---------------- fused attention ----------------
// grid: (N/64, H, B), block: 256 threads. Online softmax over 512 self keys
// (8 smem tiles of 64) + 8 per-query sim keys (streamed from gmem).
// smem: qs[64][65] + ks[64][65] + ps[64][65] + vs[64][64]  = 66304 B (dynamic)
__global__ __launch_bounds__(256) void attn_kernel(
    const float* __restrict__ q,      // (B,N,D)    pre-projection layout
    const float* __restrict__ kv,     // (B,N,2D)
    const float* __restrict__ kvsim,  // (B,N,M,2D)
    float* __restrict__ outa)         // (B,N,D)
{
    extern __shared__ float sm[];
    float* qs = sm;               // 64*65
    float* ks = qs + 64 * 65;     // 64*65
    float* ps = ks + 64 * 65;     // 64*65
    float* vs = ps + 64 * 65;     // 64*64

    const int tid = threadIdx.x;
    const int n0 = blockIdx.x * 64;
    const int h  = blockIdx.y;
    const int b  = blockIdx.z;
    const float scale = kSCALE;

    // cooperative load of Q tile (pre-scaled)
    for (int i = tid; i < 1024; i += 256) {
        int row = i >> 4;
        int c4  = (i & 15) << 2;
        float4 v = *(const float4*)&q[(size_t)(b * N_ + n0 + row) * D_ + h * DH + c4];
        float* dst = &qs[row * 65 + c4];
        dst[0] = v.x * scale; dst[1] = v.y * scale;
        dst[2] = v.z * scale; dst[3] = v.w * scale;
    }

    const int qi = tid >> 2;   // query owned for softmax/PV phase
    const int r  = tid & 3;    // sub-lane: dims r*16..r*16+15
    const int tq = tid >> 4;   // score phase: 4 queries tq*4..
    const int tk = tid & 15;   // score phase: 4 keys   tk*4..

    float m_i = -1e30f, l_i = 0.f;
    float acc[16];
    #pragma unroll
    for (int c = 0; c < 16; c++) acc[c] = 0.f;

    for (int kt = 0; kt < 8; kt++) {
        __syncthreads();
        // load K,V tile
        for (int i = tid; i < 1024; i += 256) {
            int row = i >> 4;
            int c4  = (i & 15) << 2;
            size_t gbase = (size_t)(b * N_ + kt * 64 + row) * (2 * D_) + h * DH + c4;
            float4 kk = *(const float4*)&kv[gbase];
            float* kd = &ks[row * 65 + c4];
            kd[0] = kk.x; kd[1] = kk.y; kd[2] = kk.z; kd[3] = kk.w;
            *(float4*)&vs[row * 64 + c4] = *(const float4*)&kv[gbase + D_];
        }
        __syncthreads();

        // phase A: 4x4 score microtile per thread -> raw scores to ps
        float sc[4][4];
        #pragma unroll
        for (int i = 0; i < 4; i++)
            #pragma unroll
            for (int j = 0; j < 4; j++) sc[i][j] = 0.f;
        #pragma unroll 4
        for (int d = 0; d < 64; d++) {
            float qd[4], kd[4];
            #pragma unroll
            for (int i = 0; i < 4; i++) qd[i] = qs[(tq * 4 + i) * 65 + d];
            #pragma unroll
            for (int j = 0; j < 4; j++) kd[j] = ks[(tk * 4 + j) * 65 + d];
            #pragma unroll
            for (int i = 0; i < 4; i++)
                #pragma unroll
                for (int j = 0; j < 4; j++)
                    sc[i][j] += qd[i] * kd[j];
        }
        #pragma unroll
        for (int i = 0; i < 4; i++)
            #pragma unroll
            for (int j = 0; j < 4; j++)
                ps[(tq * 4 + i) * 65 + tk * 4 + j] = sc[i][j];
        __syncthreads();

        // phase B: online softmax per (qi, r) over kj = 4j + r
        float pv[16];
        float tmax = -1e30f;
        #pragma unroll
        for (int j = 0; j < 16; j++) {
            pv[j] = ps[qi * 65 + 4 * j + r];
            tmax = fmaxf(tmax, pv[j]);
        }
        tmax = fmaxf(tmax, __shfl_xor_sync(0xffffffffu, tmax, 1));
        tmax = fmaxf(tmax, __shfl_xor_sync(0xffffffffu, tmax, 2));
        float nm   = fmaxf(m_i, tmax);
        float corr = __expf(m_i - nm);
        float psum = 0.f;
        #pragma unroll
        for (int j = 0; j < 16; j++) { pv[j] = __expf(pv[j] - nm); psum += pv[j]; }
        psum += __shfl_xor_sync(0xffffffffu, psum, 1);
        psum += __shfl_xor_sync(0xffffffffu, psum, 2);
        l_i = l_i * corr + psum;
        m_i = nm;
        #pragma unroll
        for (int c = 0; c < 16; c++) acc[c] *= corr;
        #pragma unroll
        for (int j = 0; j < 16; j++) ps[qi * 65 + 4 * j + r] = pv[j];
        __syncwarp();

        // PV accumulate (reads ps written by own warp only)
        for (int kj = 0; kj < 64; kj++) {
            float p = ps[qi * 65 + kj];
            const float* vp = &vs[kj * 64 + r * 16];
            #pragma unroll
            for (int c4 = 0; c4 < 4; c4++) {
                float4 v = *(const float4*)&vp[c4 * 4];
                acc[c4 * 4 + 0] += p * v.x;
                acc[c4 * 4 + 1] += p * v.y;
                acc[c4 * 4 + 2] += p * v.z;
                acc[c4 * 4 + 3] += p * v.w;
            }
        }
    }

    // ---- sim keys: 8 per query, each thread handles m = 2r, 2r+1 ----
    {
        size_t simbase = (size_t)(b * N_ + n0 + qi) * M_ * (2 * D_) + h * DH;
        float sc2[2];
        #pragma unroll
        for (int e = 0; e < 2; e++) {
            int m = r * 2 + e;
            const float* kp = &kvsim[simbase + (size_t)m * (2 * D_)];
            float s = 0.f;
            #pragma unroll 4
            for (int d4 = 0; d4 < 16; d4++) {
                float4 kk = *(const float4*)&kp[d4 * 4];
                const float* qp = &qs[qi * 65 + d4 * 4];
                s += qp[0] * kk.x + qp[1] * kk.y + qp[2] * kk.z + qp[3] * kk.w;
            }
            sc2[e] = s;
        }
        float tmax = fmaxf(sc2[0], sc2[1]);
        tmax = fmaxf(tmax, __shfl_xor_sync(0xffffffffu, tmax, 1));
        tmax = fmaxf(tmax, __shfl_xor_sync(0xffffffffu, tmax, 2));
        float nm   = fmaxf(m_i, tmax);
        float corr = __expf(m_i - nm);
        float p0 = __expf(sc2[0] - nm);
        float p1 = __expf(sc2[1] - nm);
        float psum = p0 + p1;
        psum += __shfl_xor_sync(0xffffffffu, psum, 1);
        psum += __shfl_xor_sync(0xffffffffu, psum, 2);
        l_i = l_i * corr + psum;
        #pragma unroll
        for (int c = 0; c < 16; c++) acc[c] *= corr;

        #pragma unroll
        for (int s4 = 0; s4 < 4; s4++) {
            float pa = __shfl_sync(0xffffffffu, p0, s4, 4);
            float pb = __shfl_sync(0xffffffffu, p1, s4, 4);
            const float* va = &kvsim[simbase + (size_t)(2 * s4) * (2 * D_) + D_ + r * 16];
            const float* vb = va + 2 * D_;
            #pragma unroll
            for (int c4 = 0; c4 < 4; c4++) {
                float4 v = *(const float4*)&va[c4 * 4];
                float4 w = *(const float4*)&vb[c4 * 4];
                acc[c4 * 4 + 0] += pa * v.x + pb * w.x;
                acc[c4 * 4 + 1] += pa * v.y + pb * w.y;
                acc[c4 * 4 + 2] += pa * v.z + pb * w.z;
                acc[c4 * 4 + 3] += pa * v.w + pb * w.w;
            }
        }
    }

    // write normalized output (B,N,D layout)
    float inv = 1.f / l_i;
    float* op = &outa[(size_t)(b * N_ + n0 + qi) * D_ + h * DH + r * 16];
    #pragma unroll
    for (int c4 = 0; c4 < 4; c4++) {
        float4 o;
        o.x = acc[c4 * 4 + 0] * inv;
        o.y = acc[c4 * 4 + 1] * inv;
        o.z = acc[c4 * 4 + 2] * inv;
        o.w = acc[c4 * 4 + 3] * inv;
        *(float4*)&op[c4 * 4] = o;
    }
}

// ---------------- launch ----------------
extern "C" void kernel_launch(void* const* d_in, const int* in_sizes, int n_in,
                              void* d_out, int out_size)
{
    const float* x   = (const float*)d_in[0];
    const float* sim = (const float*)d_in[1];
    const float* Wq  = (const float*)d_in[2];
    const float* bq  = (const float*)d_in[3];
    const float* Wkv = (const float*)d_in[4];
    const float* bkv = (const float*)d_in[5];
    const float* Wp  = (const float*)d_in[6];
    const float* bp  = (const float*)d_in[7];
    float* out = (float*)d_out;

    float *q, *kvb, *kvs, *att;
    cudaGetSymbolAddress((void**)&q,   g_q);
    cudaGetSymbolAddress((void**)&kvb, g_kv);
    cudaGetSymbolAddress((void**)&kvs, g_kvsim);
    cudaGetSymbolAddress((void**)&att, g_att);

    const int ATTN_SMEM = (3 * 64 * 65 + 64 * 64) * sizeof(float); // 66304
    cudaFuncSetAttribute(attn_kernel,
                         cudaFuncAttributeMaxDynamicSharedMemorySize, ATTN_SMEM);

    const int BN = B_ * N_;           // 8192
    const int BNM = B_ * N_ * M_;     // 65536

    // q = x @ Wq + bq
    sgemm_bias_kernel<<<dim3(D_ / 128, BN / 128), 256>>>(x, Wq, bq, q, BN, D_, D_);
    // kv = x @ Wkv + bkv
    sgemm_bias_kernel<<<dim3(2 * D_ / 128, BN / 128), 256>>>(x, Wkv, bkv, kvb, BN, 2 * D_, D_);
    // kv_sim = sim @ Wkv + bkv   (the big one: 65536 x 1536 x 768)
    sgemm_bias_kernel<<<dim3(2 * D_ / 128, BNM / 128), 256>>>(sim, Wkv, bkv, kvs, BNM, 2 * D_, D_);
    // fused attention
    attn_kernel<<<dim3(N_ / 64, H_, B_), 256, ATTN_SMEM>>>(q, kvb, kvs, att);
    // out = att @ Wp + bp
    sgemm_bias_kernel<<<dim3(D_ / 128, BN / 128), 256>>>(att, Wp, bp, out, BN, D_, D_);
}

// round 2
// speedup vs baseline: 2.0897x; 2.0897x over previous
#include <cuda_runtime.h>
#include <cstdio>

#define B_  16
#define N_  512
#define M_  8
#define D_  768
#define H_  12
#define DH  64
__device__ __constant__ float kSCALE = 0.125f; // 64^{-0.5}

// ---------------- scratch (device globals; no cudaMalloc allowed) ----------------
__device__ float g_q    [B_ * N_ * D_];              // (B,N,D)        25 MB
__device__ float g_kv   [B_ * N_ * 2 * D_];          // (B,N,2D)       50 MB
__device__ float g_kvsim[B_ * N_ * M_ * 2 * D_];     // (B,N,M,2D)    403 MB
__device__ float g_att  [B_ * N_ * D_];              // (B,N,D)        25 MB

// ---------------- tf32 helpers ----------------
__device__ __forceinline__ unsigned f2tf32(float x) {
    unsigned y;
    asm("cvt.rna.tf32.f32 %0, %1;" : "=r"(y) : "f"(x));
    return y;
}

__device__ __forceinline__ void mma_tf32(float d[4],
                                         unsigned a0, unsigned a1, unsigned a2, unsigned a3,
                                         unsigned b0, unsigned b1)
{
    asm volatile(
        "mma.sync.aligned.m16n8k8.row.col.f32.tf32.tf32.f32 "
        "{%0,%1,%2,%3}, {%4,%5,%6,%7}, {%8,%9}, {%0,%1,%2,%3};\n"
        : "+f"(d[0]), "+f"(d[1]), "+f"(d[2]), "+f"(d[3])
        : "r"(a0), "r"(a1), "r"(a2), "r"(a3), "r"(b0), "r"(b1));
}

// ---------------- tf32 tensor-core GEMM + bias ----------------
// C[M,N] = A[M,K] @ B[K,N] + bias[N]
// 128x128 block tile, BK=16, 256 threads (8 warps), warp tile 32x64.
// Requires M%128==0, N%128==0, K%16==0.
__global__ __launch_bounds__(256) void mma_gemm_bias(
    const float* __restrict__ A, const float* __restrict__ Bw,
    const float* __restrict__ bias, float* __restrict__ C,
    int M, int N, int K)
{
    __shared__ unsigned As[16][136];   // [k][m], padded stride -> conflict-free frags
    __shared__ unsigned Bs[16][136];   // [k][n]

    const int tid  = threadIdx.x;
    const int warp = tid >> 5;
    const int lane = tid & 31;
    const int gid  = lane >> 2;   // 0..7
    const int tig  = lane & 3;    // 0..3
    const int wm   = (warp >> 1) * 32;   // warp M offset in tile (0..96)
    const int wn   = (warp & 1)  * 64;   // warp N offset in tile (0 or 64)
    const int bm   = blockIdx.y * 128;
    const int bn   = blockIdx.x * 128;

    // gmem load mapping (per k-tile: A 128x16, B 16x128, each 512 float4)
    // A: idx = tid + i*256: arow = idx>>2 (0..127), akq = (idx&3)*4
    // B: idx = tid + i*256: bkr  = idx>>5 (0..15),  bcl = (idx&31)*4
    const int arow0 = tid >> 2;
    const int akq   = (tid & 3) << 2;
    const int bkr0  = tid >> 5;
    const int bcl   = (tid & 31) << 2;

    const float* Ap = A + (size_t)(bm + arow0) * K + akq;        // +64 rows for i=1
    const float* Bp = Bw + (size_t)bkr0 * N + bn + bcl;          // +8 k-rows for i=1

    float acc[2][8][4];
    #pragma unroll
    for (int mt = 0; mt < 2; mt++)
        #pragma unroll
        for (int nt = 0; nt < 8; nt++)
            #pragma unroll
            for (int c = 0; c < 4; c++) acc[mt][nt][c] = 0.f;

    float4 apre[2], bpre[2];

    // prologue: tile 0
    apre[0] = *(const float4*)&Ap[0];
    apre[1] = *(const float4*)&Ap[(size_t)64 * K];
    bpre[0] = *(const float4*)&Bp[0];
    bpre[1] = *(const float4*)&Bp[(size_t)8 * N];

    #pragma unroll
    for (int i = 0; i < 2; i++) {
        int ar = arow0 + i * 64;
        As[akq + 0][ar] = f2tf32(apre[i].x);
        As[akq + 1][ar] = f2tf32(apre[i].y);
        As[akq + 2][ar] = f2tf32(apre[i].z);
        As[akq + 3][ar] = f2tf32(apre[i].w);
        uint4 bv;
        bv.x = f2tf32(bpre[i].x); bv.y = f2tf32(bpre[i].y);
        bv.z = f2tf32(bpre[i].z); bv.w = f2tf32(bpre[i].w);
        *(uint4*)&Bs[bkr0 + i * 8][bcl] = bv;
    }
    __syncthreads();

    for (int k0 = 16; k0 <= K; k0 += 16) {
        // prefetch next tile (if any)
        if (k0 < K) {
            apre[0] = *(const float4*)&Ap[k0];
            apre[1] = *(const float4*)&Ap[(size_t)64 * K + k0];
            bpre[0] = *(const float4*)&Bp[(size_t)k0 * N];
            bpre[1] = *(const float4*)&Bp[(size_t)(k0 + 8) * N];
        }

        // compute on current smem tile
        #pragma unroll
        for (int ks = 0; ks < 2; ks++) {
            const int kb = ks * 8;
            unsigned afr[2][4];
            #pragma unroll
            for (int mt = 0; mt < 2; mt++) {
                const int row = wm + mt * 16 + gid;
                afr[mt][0] = As[kb + tig][row];
                afr[mt][1] = As[kb + tig][row + 8];
                afr[mt][2] = As[kb + tig + 4][row];
                afr[mt][3] = As[kb + tig + 4][row + 8];
            }
            unsigned bfr[8][2];
            #pragma unroll
            for (int nt = 0; nt < 8; nt++) {
                const int col = wn + nt * 8 + gid;
                bfr[nt][0] = Bs[kb + tig][col];
                bfr[nt][1] = Bs[kb + tig + 4][col];
            }
            #pragma unroll
            for (int mt = 0; mt < 2; mt++)
                #pragma unroll
                for (int nt = 0; nt < 8; nt++)
                    mma_tf32(acc[mt][nt],
                             afr[mt][0], afr[mt][1], afr[mt][2], afr[mt][3],
                             bfr[nt][0], bfr[nt][1]);
        }
        __syncthreads();

        if (k0 < K) {
            #pragma unroll
            for (int i = 0; i < 2; i++) {
                int ar = arow0 + i * 64;
                As[akq + 0][ar] = f2tf32(apre[i].x);
                As[akq + 1][ar] = f2tf32(apre[i].y);
                As[akq + 2][ar] = f2tf32(apre[i].z);
                As[akq + 3][ar] = f2tf32(apre[i].w);
                uint4 bv;
                bv.x = f2tf32(bpre[i].x); bv.y = f2tf32(bpre[i].y);
                bv.z = f2tf32(bpre[i].z); bv.w = f2tf32(bpre[i].w);
                *(uint4*)&Bs[bkr0 + i * 8][bcl] = bv;
            }
            __syncthreads();
        }
    }

    // epilogue: bias + store (float2 per row pair)
    #pragma unroll
    for (int mt = 0; mt < 2; mt++) {
        const int row0 = bm + wm + mt * 16 + gid;
        #pragma unroll
        for (int nt = 0; nt < 8; nt++) {
            const int col = bn + wn + nt * 8 + 2 * tig;
            const float b0 = bias[col], b1 = bias[col + 1];
            float2 o0, o1;
            o0.x = acc[mt][nt][0] + b0;
            o0.y = acc[mt][nt][1] + b1;
            o1.x = acc[mt][nt][2] + b0;
            o1.y = acc[mt][nt][3] + b1;
            *(float2*)&C[(size_t)row0 * N + col]       = o0;
            *(float2*)&C[(size_t)(row0 + 8) * N + col] = o1;
        }
    }
}

// ---------------- fused attention (unchanged from round 1) ----------------
__global__ __launch_bounds__(256) void attn_kernel(
    const float* __restrict__ q,      // (B,N,D)
    const float* __restrict__ kv,     // (B,N,2D)
    const float* __restrict__ kvsim,  // (B,N,M,2D)
    float* __restrict__ outa)         // (B,N,D)
{
    extern __shared__ float sm[];
    float* qs = sm;               // 64*65
    float* ks = qs + 64 * 65;     // 64*65
    float* ps = ks + 64 * 65;     // 64*65
    float* vs = ps + 64 * 65;     // 64*64

    const int tid = threadIdx.x;
    const int n0 = blockIdx.x * 64;
    const int h  = blockIdx.y;
    const int b  = blockIdx.z;
    const float scale = kSCALE;

    for (int i = tid; i < 1024; i += 256) {
        int row = i >> 4;
        int c4  = (i & 15) << 2;
        float4 v = *(const float4*)&q[(size_t)(b * N_ + n0 + row) * D_ + h * DH + c4];
        float* dst = &qs[row * 65 + c4];
        dst[0] = v.x * scale; dst[1] = v.y * scale;
        dst[2] = v.z * scale; dst[3] = v.w * scale;
    }

    const int qi = tid >> 2;
    const int r  = tid & 3;
    const int tq = tid >> 4;
    const int tk = tid & 15;

    float m_i = -1e30f, l_i = 0.f;
    float acc[16];
    #pragma unroll
    for (int c = 0; c < 16; c++) acc[c] = 0.f;

    for (int kt = 0; kt < 8; kt++) {
        __syncthreads();
        for (int i = tid; i < 1024; i += 256) {
            int row = i >> 4;
            int c4  = (i & 15) << 2;
            size_t gbase = (size_t)(b * N_ + kt * 64 + row) * (2 * D_) + h * DH + c4;
            float4 kk = *(const float4*)&kv[gbase];
            float* kd = &ks[row * 65 + c4];
            kd[0] = kk.x; kd[1] = kk.y; kd[2] = kk.z; kd[3] = kk.w;
            *(float4*)&vs[row * 64 + c4] = *(const float4*)&kv[gbase + D_];
        }
        __syncthreads();

        float sc[4][4];
        #pragma unroll
        for (int i = 0; i < 4; i++)
            #pragma unroll
            for (int j = 0; j < 4; j++) sc[i][j] = 0.f;
        #pragma unroll 4
        for (int d = 0; d < 64; d++) {
            float qd[4], kd[4];
            #pragma unroll
            for (int i = 0; i < 4; i++) qd[i] = qs[(tq * 4 + i) * 65 + d];
            #pragma unroll
            for (int j = 0; j < 4; j++) kd[j] = ks[(tk * 4 + j) * 65 + d];
            #pragma unroll
            for (int i = 0; i < 4; i++)
                #pragma unroll
                for (int j = 0; j < 4; j++)
                    sc[i][j] += qd[i] * kd[j];
        }
        #pragma unroll
        for (int i = 0; i < 4; i++)
            #pragma unroll
            for (int j = 0; j < 4; j++)
                ps[(tq * 4 + i) * 65 + tk * 4 + j] = sc[i][j];
        __syncthreads();

        float pv[16];
        float tmax = -1e30f;
        #pragma unroll
        for (int j = 0; j < 16; j++) {
            pv[j] = ps[qi * 65 + 4 * j + r];
            tmax = fmaxf(tmax, pv[j]);
        }
        tmax = fmaxf(tmax, __shfl_xor_sync(0xffffffffu, tmax, 1));
        tmax = fmaxf(tmax, __shfl_xor_sync(0xffffffffu, tmax, 2));
        float nm   = fmaxf(m_i, tmax);
        float corr = __expf(m_i - nm);
        float psum = 0.f;
        #pragma unroll
        for (int j = 0; j < 16; j++) { pv[j] = __expf(pv[j] - nm); psum += pv[j]; }
        psum += __shfl_xor_sync(0xffffffffu, psum, 1);
        psum += __shfl_xor_sync(0xffffffffu, psum, 2);
        l_i = l_i * corr + psum;
        m_i = nm;
        #pragma unroll
        for (int c = 0; c < 16; c++) acc[c] *= corr;
        #pragma unroll
        for (int j = 0; j < 16; j++) ps[qi * 65 + 4 * j + r] = pv[j];
        __syncwarp();

        for (int kj = 0; kj < 64; kj++) {
            float p = ps[qi * 65 + kj];
            const float* vp = &vs[kj * 64 + r * 16];
            #pragma unroll
            for (int c4 = 0; c4 < 4; c4++) {
                float4 v = *(const float4*)&vp[c4 * 4];
                acc[c4 * 4 + 0] += p * v.x;
                acc[c4 * 4 + 1] += p * v.y;
                acc[c4 * 4 + 2] += p * v.z;
                acc[c4 * 4 + 3] += p * v.w;
            }
        }
    }

    {
        size_t simbase = (size_t)(b * N_ + n0 + qi) * M_ * (2 * D_) + h * DH;
        float sc2[2];
        #pragma unroll
        for (int e = 0; e < 2; e++) {
            int m = r * 2 + e;
            const float* kp = &kvsim[simbase + (size_t)m * (2 * D_)];
            float s = 0.f;
            #pragma unroll 4
            for (int d4 = 0; d4 < 16; d4++) {
                float4 kk = *(const float4*)&kp[d4 * 4];
                const float* qp = &qs[qi * 65 + d4 * 4];
                s += qp[0] * kk.x + qp[1] * kk.y + qp[2] * kk.z + qp[3] * kk.w;
            }
            sc2[e] = s;
        }
        float tmax = fmaxf(sc2[0], sc2[1]);
        tmax = fmaxf(tmax, __shfl_xor_sync(0xffffffffu, tmax, 1));
        tmax = fmaxf(tmax, __shfl_xor_sync(0xffffffffu, tmax, 2));
        float nm   = fmaxf(m_i, tmax);
        float corr = __expf(m_i - nm);
        float p0 = __expf(sc2[0] - nm);
        float p1 = __expf(sc2[1] - nm);
        float psum = p0 + p1;
        psum += __shfl_xor_sync(0xffffffffu, psum, 1);
        psum += __shfl_xor_sync(0xffffffffu, psum, 2);
        l_i = l_i * corr + psum;
        #pragma unroll
        for (int c = 0; c < 16; c++) acc[c] *= corr;

        #pragma unroll
        for (int s4 = 0; s4 < 4; s4++) {
            float pa = __shfl_sync(0xffffffffu, p0, s4, 4);
            float pb = __shfl_sync(0xffffffffu, p1, s4, 4);
            const float* va = &kvsim[simbase + (size_t)(2 * s4) * (2 * D_) + D_ + r * 16];
            const float* vb = va + 2 * D_;
            #pragma unroll
            for (int c4 = 0; c4 < 4; c4++) {
                float4 v = *(const float4*)&va[c4 * 4];
                float4 w = *(const float4*)&vb[c4 * 4];
                acc[c4 * 4 + 0] += pa * v.x + pb * w.x;
                acc[c4 * 4 + 1] += pa * v.y + pb * w.y;
                acc[c4 * 4 + 2] += pa * v.z + pb * w.z;
                acc[c4 * 4 + 3] += pa * v.w + pb * w.w;
            }
        }
    }

    float inv = 1.f / l_i;
    float* op = &outa[(size_t)(b * N_ + n0 + qi) * D_ + h * DH + r * 16];
    #pragma unroll
    for (int c4 = 0; c4 < 4; c4++) {
        float4 o;
        o.x = acc[c4 * 4 + 0] * inv;
        o.y = acc[c4 * 4 + 1] * inv;
        o.z = acc[c4 * 4 + 2] * inv;
        o.w = acc[c4 * 4 + 3] * inv;
        *(float4*)&op[c4 * 4] = o;
    }
}

// ---------------- launch ----------------
extern "C" void kernel_launch(void* const* d_in, const int* in_sizes, int n_in,
                              void* d_out, int out_size)
{
    const float* x   = (const float*)d_in[0];
    const float* sim = (const float*)d_in[1];
    const float* Wq  = (const float*)d_in[2];
    const float* bq  = (const float*)d_in[3];
    const float* Wkv = (const float*)d_in[4];
    const float* bkv = (const float*)d_in[5];
    const float* Wp  = (const float*)d_in[6];
    const float* bp  = (const float*)d_in[7];
    float* out = (float*)d_out;

    float *q, *kvb, *kvs, *att;
    cudaGetSymbolAddress((void**)&q,   g_q);
    cudaGetSymbolAddress((void**)&kvb, g_kv);
    cudaGetSymbolAddress((void**)&kvs, g_kvsim);
    cudaGetSymbolAddress((void**)&att, g_att);

    const int ATTN_SMEM = (3 * 64 * 65 + 64 * 64) * sizeof(float); // 66304
    cudaFuncSetAttribute(attn_kernel,
                         cudaFuncAttributeMaxDynamicSharedMemorySize, ATTN_SMEM);

    const int BN  = B_ * N_;          // 8192
    const int BNM = B_ * N_ * M_;     // 65536

    mma_gemm_bias<<<dim3(D_ / 128, BN / 128), 256>>>(x, Wq, bq, q, BN, D_, D_);
    mma_gemm_bias<<<dim3(2 * D_ / 128, BN / 128), 256>>>(x, Wkv, bkv, kvb, BN, 2 * D_, D_);
    mma_gemm_bias<<<dim3(2 * D_ / 128, BNM / 128), 256>>>(sim, Wkv, bkv, kvs, BNM, 2 * D_, D_);
    attn_kernel<<<dim3(N_ / 64, H_, B_), 256, ATTN_SMEM>>>(q, kvb, kvs, att);
    mma_gemm_bias<<<dim3(D_ / 128, BN / 128), 256>>>(att, Wp, bp, out, BN, D_, D_);
}

// round 3
// speedup vs baseline: 2.3373x; 1.1185x over previous
#include <cuda_runtime.h>
#include <cstdio>

#define B_  16
#define N_  512
#define M_  8
#define D_  768
#define H_  12
#define DH  64
__device__ __constant__ float kSCALE = 0.125f; // 64^{-0.5}

// ---------------- scratch (device globals; no cudaMalloc allowed) ----------------
__device__ float g_q    [B_ * N_ * D_];              // (B,N,D)        25 MB
__device__ float g_kv   [B_ * N_ * 2 * D_];          // (B,N,2D)       50 MB
__device__ float g_kvsim[B_ * N_ * M_ * 2 * D_];     // (B,N,M,2D)    403 MB
__device__ float g_att  [B_ * N_ * D_];              // (B,N,D)        25 MB

// ---------------- tf32 / cp.async helpers ----------------
__device__ __forceinline__ unsigned f2tf32(float x) {
    unsigned y;
    asm("cvt.rna.tf32.f32 %0, %1;" : "=r"(y) : "f"(x));
    return y;
}

__device__ __forceinline__ void mma_tf32(float d[4],
                                         unsigned a0, unsigned a1, unsigned a2, unsigned a3,
                                         unsigned b0, unsigned b1)
{
    asm volatile(
        "mma.sync.aligned.m16n8k8.row.col.f32.tf32.tf32.f32 "
        "{%0,%1,%2,%3}, {%4,%5,%6,%7}, {%8,%9}, {%0,%1,%2,%3};\n"
        : "+f"(d[0]), "+f"(d[1]), "+f"(d[2]), "+f"(d[3])
        : "r"(a0), "r"(a1), "r"(a2), "r"(a3), "r"(b0), "r"(b1));
}

__device__ __forceinline__ void cp16(float* smem_dst, const float* gmem_src) {
    unsigned s = (unsigned)__cvta_generic_to_shared(smem_dst);
    asm volatile("cp.async.cg.shared.global [%0], [%1], 16;\n"
                 :: "r"(s), "l"(gmem_src));
}
#define CP_COMMIT() asm volatile("cp.async.commit_group;\n" ::: "memory")
#define CP_WAIT1()  asm volatile("cp.async.wait_group 1;\n" ::: "memory")

// ---------------- tf32 tensor-core GEMM + bias, 2-stage cp.async pipeline -------
// C[M,N] = A[M,K] @ B[K,N] + bias[N]
// 128x128 block tile, BK=16, 256 threads (8 warps), warp tile 32x64.
// As: [m][k] stride 20 (20 mod 32 == 4 -> A-frag LDS conflict-free)
// Bs: [k][n] stride 136 (136 mod 32 == 8 -> B-frag LDS conflict-free)
// Requires M%128==0, N%128==0, K%16==0.
#define SA 20
#define SB 136
__global__ __launch_bounds__(256, 2) void mma_gemm_bias(
    const float* __restrict__ A, const float* __restrict__ Bw,
    const float* __restrict__ bias, float* __restrict__ C,
    int M, int N, int K)
{
    __shared__ float As[2][128 * SA];
    __shared__ float Bs[2][16 * SB];

    const int tid  = threadIdx.x;
    const int warp = tid >> 5;
    const int lane = tid & 31;
    const int gid  = lane >> 2;   // 0..7
    const int tig  = lane & 3;    // 0..3
    const int wm   = (warp >> 1) * 32;   // 0,32,64,96
    const int wn   = (warp & 1)  * 64;   // 0,64
    const int bm   = blockIdx.y * 128;
    const int bn   = blockIdx.x * 128;

    // copy mapping: A tile 128x16 = 512 x 16B; B tile 16x128 = 512 x 16B
    const int arow = tid >> 2;          // 0..63 (+64)
    const int akq  = (tid & 3) << 2;    // 0,4,8,12
    const int bkr  = tid >> 5;          // 0..7 (+8)
    const int bcl  = (tid & 31) << 2;   // 0..124

    const float* Agp = A  + (size_t)(bm + arow) * K + akq;
    const float* Bgp = Bw + (size_t)bkr * N + bn + bcl;
    const size_t a64 = (size_t)64 * K;
    const size_t b8  = (size_t)8 * N;

    float acc[2][8][4];
    #pragma unroll
    for (int mt = 0; mt < 2; mt++)
        #pragma unroll
        for (int nt = 0; nt < 8; nt++)
            #pragma unroll
            for (int c = 0; c < 4; c++) acc[mt][nt][c] = 0.f;

    // prologue: stage 0
    cp16(&As[0][arow * SA + akq],        Agp);
    cp16(&As[0][(arow + 64) * SA + akq], Agp + a64);
    cp16(&Bs[0][bkr * SB + bcl],         Bgp);
    cp16(&Bs[0][(bkr + 8) * SB + bcl],   Bgp + b8);
    CP_COMMIT();

    int cur = 0;
    for (int k0 = 0; k0 < K; k0 += 16) {
        // issue next stage's copies (overlaps with this tile's compute)
        if (k0 + 16 < K) {
            const int nx = cur ^ 1;
            cp16(&As[nx][arow * SA + akq],        Agp + k0 + 16);
            cp16(&As[nx][(arow + 64) * SA + akq], Agp + a64 + k0 + 16);
            cp16(&Bs[nx][bkr * SB + bcl],         Bgp + (size_t)(k0 + 16) * N);
            cp16(&Bs[nx][(bkr + 8) * SB + bcl],   Bgp + b8 + (size_t)(k0 + 16) * N);
        }
        CP_COMMIT();
        CP_WAIT1();                 // stage `cur` complete (newest group may fly)
        __syncthreads();

        const float* as = As[cur];
        const float* bs = Bs[cur];
        #pragma unroll
        for (int ks = 0; ks < 2; ks++) {
            const int kb = ks * 8;
            unsigned afr[2][4];
            #pragma unroll
            for (int mt = 0; mt < 2; mt++) {
                const int row = wm + mt * 16 + gid;
                afr[mt][0] = f2tf32(as[row * SA + kb + tig]);
                afr[mt][1] = f2tf32(as[(row + 8) * SA + kb + tig]);
                afr[mt][2] = f2tf32(as[row * SA + kb + tig + 4]);
                afr[mt][3] = f2tf32(as[(row + 8) * SA + kb + tig + 4]);
            }
            unsigned bfr[8][2];
            #pragma unroll
            for (int nt = 0; nt < 8; nt++) {
                const int col = wn + nt * 8 + gid;
                bfr[nt][0] = f2tf32(bs[(kb + tig) * SB + col]);
                bfr[nt][1] = f2tf32(bs[(kb + tig + 4) * SB + col]);
            }
            #pragma unroll
            for (int mt = 0; mt < 2; mt++)
                #pragma unroll
                for (int nt = 0; nt < 8; nt++)
                    mma_tf32(acc[mt][nt],
                             afr[mt][0], afr[mt][1], afr[mt][2], afr[mt][3],
                             bfr[nt][0], bfr[nt][1]);
        }
        __syncthreads();            // protect stage `cur` before it is refilled
        cur ^= 1;
    }

    // epilogue: bias + store
    #pragma unroll
    for (int mt = 0; mt < 2; mt++) {
        const int row0 = bm + wm + mt * 16 + gid;
        #pragma unroll
        for (int nt = 0; nt < 8; nt++) {
            const int col = bn + wn + nt * 8 + 2 * tig;
            const float b0 = bias[col], b1 = bias[col + 1];
            float2 o0, o1;
            o0.x = acc[mt][nt][0] + b0;
            o0.y = acc[mt][nt][1] + b1;
            o1.x = acc[mt][nt][2] + b0;
            o1.y = acc[mt][nt][3] + b1;
            *(float2*)&C[(size_t)row0 * N + col]       = o0;
            *(float2*)&C[(size_t)(row0 + 8) * N + col] = o1;
        }
    }
}

// ---------------- fused attention (unchanged) ----------------
__global__ __launch_bounds__(256) void attn_kernel(
    const float* __restrict__ q,      // (B,N,D)
    const float* __restrict__ kv,     // (B,N,2D)
    const float* __restrict__ kvsim,  // (B,N,M,2D)
    float* __restrict__ outa)         // (B,N,D)
{
    extern __shared__ float sm[];
    float* qs = sm;               // 64*65
    float* ks = qs + 64 * 65;     // 64*65
    float* ps = ks + 64 * 65;     // 64*65
    float* vs = ps + 64 * 65;     // 64*64

    const int tid = threadIdx.x;
    const int n0 = blockIdx.x * 64;
    const int h  = blockIdx.y;
    const int b  = blockIdx.z;
    const float scale = kSCALE;

    for (int i = tid; i < 1024; i += 256) {
        int row = i >> 4;
        int c4  = (i & 15) << 2;
        float4 v = *(const float4*)&q[(size_t)(b * N_ + n0 + row) * D_ + h * DH + c4];
        float* dst = &qs[row * 65 + c4];
        dst[0] = v.x * scale; dst[1] = v.y * scale;
        dst[2] = v.z * scale; dst[3] = v.w * scale;
    }

    const int qi = tid >> 2;
    const int r  = tid & 3;
    const int tq = tid >> 4;
    const int tk = tid & 15;

    float m_i = -1e30f, l_i = 0.f;
    float acc[16];
    #pragma unroll
    for (int c = 0; c < 16; c++) acc[c] = 0.f;

    for (int kt = 0; kt < 8; kt++) {
        __syncthreads();
        for (int i = tid; i < 1024; i += 256) {
            int row = i >> 4;
            int c4  = (i & 15) << 2;
            size_t gbase = (size_t)(b * N_ + kt * 64 + row) * (2 * D_) + h * DH + c4;
            float4 kk = *(const float4*)&kv[gbase];
            float* kd = &ks[row * 65 + c4];
            kd[0] = kk.x; kd[1] = kk.y; kd[2] = kk.z; kd[3] = kk.w;
            *(float4*)&vs[row * 64 + c4] = *(const float4*)&kv[gbase + D_];
        }
        __syncthreads();

        float sc[4][4];
        #pragma unroll
        for (int i = 0; i < 4; i++)
            #pragma unroll
            for (int j = 0; j < 4; j++) sc[i][j] = 0.f;
        #pragma unroll 4
        for (int d = 0; d < 64; d++) {
            float qd[4], kd[4];
            #pragma unroll
            for (int i = 0; i < 4; i++) qd[i] = qs[(tq * 4 + i) * 65 + d];
            #pragma unroll
            for (int j = 0; j < 4; j++) kd[j] = ks[(tk * 4 + j) * 65 + d];
            #pragma unroll
            for (int i = 0; i < 4; i++)
                #pragma unroll
                for (int j = 0; j < 4; j++)
                    sc[i][j] += qd[i] * kd[j];
        }
        #pragma unroll
        for (int i = 0; i < 4; i++)
            #pragma unroll
            for (int j = 0; j < 4; j++)
                ps[(tq * 4 + i) * 65 + tk * 4 + j] = sc[i][j];
        __syncthreads();

        float pv[16];
        float tmax = -1e30f;
        #pragma unroll
        for (int j = 0; j < 16; j++) {
            pv[j] = ps[qi * 65 + 4 * j + r];
            tmax = fmaxf(tmax, pv[j]);
        }
        tmax = fmaxf(tmax, __shfl_xor_sync(0xffffffffu, tmax, 1));
        tmax = fmaxf(tmax, __shfl_xor_sync(0xffffffffu, tmax, 2));
        float nm   = fmaxf(m_i, tmax);
        float corr = __expf(m_i - nm);
        float psum = 0.f;
        #pragma unroll
        for (int j = 0; j < 16; j++) { pv[j] = __expf(pv[j] - nm); psum += pv[j]; }
        psum += __shfl_xor_sync(0xffffffffu, psum, 1);
        psum += __shfl_xor_sync(0xffffffffu, psum, 2);
        l_i = l_i * corr + psum;
        m_i = nm;
        #pragma unroll
        for (int c = 0; c < 16; c++) acc[c] *= corr;
        #pragma unroll
        for (int j = 0; j < 16; j++) ps[qi * 65 + 4 * j + r] = pv[j];
        __syncwarp();

        for (int kj = 0; kj < 64; kj++) {
            float p = ps[qi * 65 + kj];
            const float* vp = &vs[kj * 64 + r * 16];
            #pragma unroll
            for (int c4 = 0; c4 < 4; c4++) {
                float4 v = *(const float4*)&vp[c4 * 4];
                acc[c4 * 4 + 0] += p * v.x;
                acc[c4 * 4 + 1] += p * v.y;
                acc[c4 * 4 + 2] += p * v.z;
                acc[c4 * 4 + 3] += p * v.w;
            }
        }
    }

    {
        size_t simbase = (size_t)(b * N_ + n0 + qi) * M_ * (2 * D_) + h * DH;
        float sc2[2];
        #pragma unroll
        for (int e = 0; e < 2; e++) {
            int m = r * 2 + e;
            const float* kp = &kvsim[simbase + (size_t)m * (2 * D_)];
            float s = 0.f;
            #pragma unroll 4
            for (int d4 = 0; d4 < 16; d4++) {
                float4 kk = *(const float4*)&kp[d4 * 4];
                const float* qp = &qs[qi * 65 + d4 * 4];
                s += qp[0] * kk.x + qp[1] * kk.y + qp[2] * kk.z + qp[3] * kk.w;
            }
            sc2[e] = s;
        }
        float tmax = fmaxf(sc2[0], sc2[1]);
        tmax = fmaxf(tmax, __shfl_xor_sync(0xffffffffu, tmax, 1));
        tmax = fmaxf(tmax, __shfl_xor_sync(0xffffffffu, tmax, 2));
        float nm   = fmaxf(m_i, tmax);
        float corr = __expf(m_i - nm);
        float p0 = __expf(sc2[0] - nm);
        float p1 = __expf(sc2[1] - nm);
        float psum = p0 + p1;
        psum += __shfl_xor_sync(0xffffffffu, psum, 1);
        psum += __shfl_xor_sync(0xffffffffu, psum, 2);
        l_i = l_i * corr + psum;
        #pragma unroll
        for (int c = 0; c < 16; c++) acc[c] *= corr;

        #pragma unroll
        for (int s4 = 0; s4 < 4; s4++) {
            float pa = __shfl_sync(0xffffffffu, p0, s4, 4);
            float pb = __shfl_sync(0xffffffffu, p1, s4, 4);
            const float* va = &kvsim[simbase + (size_t)(2 * s4) * (2 * D_) + D_ + r * 16];
            const float* vb = va + 2 * D_;
            #pragma unroll
            for (int c4 = 0; c4 < 4; c4++) {
                float4 v = *(const float4*)&va[c4 * 4];
                float4 w = *(const float4*)&vb[c4 * 4];
                acc[c4 * 4 + 0] += pa * v.x + pb * w.x;
                acc[c4 * 4 + 1] += pa * v.y + pb * w.y;
                acc[c4 * 4 + 2] += pa * v.z + pb * w.z;
                acc[c4 * 4 + 3] += pa * v.w + pb * w.w;
            }
        }
    }

    float inv = 1.f / l_i;
    float* op = &outa[(size_t)(b * N_ + n0 + qi) * D_ + h * DH + r * 16];
    #pragma unroll
    for (int c4 = 0; c4 < 4; c4++) {
        float4 o;
        o.x = acc[c4 * 4 + 0] * inv;
        o.y = acc[c4 * 4 + 1] * inv;
        o.z = acc[c4 * 4 + 2] * inv;
        o.w = acc[c4 * 4 + 3] * inv;
        *(float4*)&op[c4 * 4] = o;
    }
}

// ---------------- launch ----------------
extern "C" void kernel_launch(void* const* d_in, const int* in_sizes, int n_in,
                              void* d_out, int out_size)
{
    const float* x   = (const float*)d_in[0];
    const float* sim = (const float*)d_in[1];
    const float* Wq  = (const float*)d_in[2];
    const float* bq  = (const float*)d_in[3];
    const float* Wkv = (const float*)d_in[4];
    const float* bkv = (const float*)d_in[5];
    const float* Wp  = (const float*)d_in[6];
    const float* bp  = (const float*)d_in[7];
    float* out = (float*)d_out;

    float *q, *kvb, *kvs, *att;
    cudaGetSymbolAddress((void**)&q,   g_q);
    cudaGetSymbolAddress((void**)&kvb, g_kv);
    cudaGetSymbolAddress((void**)&kvs, g_kvsim);
    cudaGetSymbolAddress((void**)&att, g_att);

    const int ATTN_SMEM = (3 * 64 * 65 + 64 * 64) * sizeof(float); // 66304
    cudaFuncSetAttribute(attn_kernel,
                         cudaFuncAttributeMaxDynamicSharedMemorySize, ATTN_SMEM);

    const int BN  = B_ * N_;          // 8192
    const int BNM = B_ * N_ * M_;     // 65536

    mma_gemm_bias<<<dim3(D_ / 128, BN / 128), 256>>>(x, Wq, bq, q, BN, D_, D_);
    mma_gemm_bias<<<dim3(2 * D_ / 128, BN / 128), 256>>>(x, Wkv, bkv, kvb, BN, 2 * D_, D_);
    mma_gemm_bias<<<dim3(2 * D_ / 128, BNM / 128), 256>>>(sim, Wkv, bkv, kvs, BNM, 2 * D_, D_);
    attn_kernel<<<dim3(N_ / 64, H_, B_), 256, ATTN_SMEM>>>(q, kvb, kvs, att);
    mma_gemm_bias<<<dim3(D_ / 128, BN / 128), 256>>>(att, Wp, bp, out, BN, D_, D_);
}

// round 5
// speedup vs baseline: 2.8721x; 1.2288x over previous
#include <cuda_runtime.h>
#include <cuda_fp16.h>
#include <cstdint>
#include <cstdio>

#define B_  16
#define N_  512
#define M_  8
#define D_  768
#define H_  12
#define DH  64
__device__ __constant__ float kSCALE = 0.125f; // 64^{-0.5}

// ---------------- scratch (device globals; no cudaMalloc allowed) ----------------
__device__ float  g_q    [B_ * N_ * D_];              // (B,N,D) fp32
__device__ float  g_kv   [B_ * N_ * 2 * D_];          // (B,N,2D) fp32
__device__ float  g_kvsim[B_ * N_ * M_ * 2 * D_];     // (B,N,M,2D) fp32
__device__ __half g_att  [B_ * N_ * D_];              // (B,N,D) half (feeds last GEMM)
__device__ __half g_xh   [B_ * N_ * D_];              // x in half
__device__ __half g_simh [B_ * N_ * M_ * D_];         // sim in half
__device__ __half g_wqt  [D_ * D_];                   // Wq^T  [N][K] half
__device__ __half g_wkvt [2 * D_ * D_];               // Wkv^T [2D][D] half
__device__ __half g_wpt  [D_ * D_];                   // Wp^T half

// ---------------- helpers ----------------
__device__ __forceinline__ void cp16(void* smem_dst, const void* gmem_src) {
    unsigned s = (unsigned)__cvta_generic_to_shared(smem_dst);
    asm volatile("cp.async.cg.shared.global [%0], [%1], 16;\n"
                 :: "r"(s), "l"(gmem_src));
}
#define CP_COMMIT() asm volatile("cp.async.commit_group;\n" ::: "memory")
#define CP_WAIT1()  asm volatile("cp.async.wait_group 1;\n" ::: "memory")

__device__ __forceinline__ void mma_f16(float d[4],
                                        unsigned a0, unsigned a1, unsigned a2, unsigned a3,
                                        unsigned b0, unsigned b1)
{
    asm volatile(
        "mma.sync.aligned.m16n8k16.row.col.f32.f16.f16.f32 "
        "{%0,%1,%2,%3}, {%4,%5,%6,%7}, {%8,%9}, {%0,%1,%2,%3};\n"
        : "+f"(d[0]), "+f"(d[1]), "+f"(d[2]), "+f"(d[3])
        : "r"(a0), "r"(a1), "r"(a2), "r"(a3), "r"(b0), "r"(b1));
}

// ---------------- prep kernels ----------------
__global__ void f2h_kernel(const float* __restrict__ in,
                           __half* __restrict__ out, int n4) {
    int i = blockIdx.x * blockDim.x + threadIdx.x;
    if (i < n4) {
        float4 v = ((const float4*)in)[i];
        __half2 h0 = __floats2half2_rn(v.x, v.y);
        __half2 h1 = __floats2half2_rn(v.z, v.w);
        ((__half2*)out)[2 * i]     = h0;
        ((__half2*)out)[2 * i + 1] = h1;
    }
}

// Wt[n][k] = half(W[k][n]); K rows, N cols; K,N multiples of 32
__global__ void transpose_h_kernel(const float* __restrict__ W,
                                   __half* __restrict__ Wt, int K, int N) {
    __shared__ float t[32][33];
    int k0 = blockIdx.y * 32, n0 = blockIdx.x * 32;
    int x = threadIdx.x, y = threadIdx.y;          // block (32,8)
    #pragma unroll
    for (int i = 0; i < 32; i += 8)
        t[y + i][x] = W[(size_t)(k0 + y + i) * N + n0 + x];
    __syncthreads();
    #pragma unroll
    for (int i = 0; i < 32; i += 8)
        Wt[(size_t)(n0 + y + i) * K + k0 + x] = __float2half_rn(t[x][y + i]);
}

// ---------------- fp16 tensor-core GEMM + bias, 2-stage cp.async pipeline ------
// C[M,N] = A[M,K] @ Bt[N,K]^T + bias[N]   (A, Bt half; C, bias fp32)
// 128x128 block tile, BK=32 halves, 256 threads (8 warps), warp tile 32x64.
// As/Bs: [row][k] halves, stride SA=40 halves (80B) -> conflict-free LDS.32
// Requires M%128==0, N%128==0, K%32==0.
#define SA 40
__global__ __launch_bounds__(256, 2) void hgemm_bias(
    const __half* __restrict__ A, const __half* __restrict__ Bt,
    const float* __restrict__ bias, float* __restrict__ C,
    int Mdim, int Ndim, int Kdim)
{
    __shared__ __half As[2][128 * SA];
    __shared__ __half Bs[2][128 * SA];

    const int tid  = threadIdx.x;
    const int warp = tid >> 5;
    const int lane = tid & 31;
    const int gid  = lane >> 2;   // 0..7
    const int tig  = lane & 3;    // 0..3
    const int wm   = (warp >> 1) * 32;   // 0,32,64,96
    const int wn   = (warp & 1)  * 64;   // 0,64
    const int bm   = blockIdx.y * 128;
    const int bn   = blockIdx.x * 128;

    // copy mapping: per stage each tile is 128 rows x 64B = 512 x 16B granules
    const int crow = tid >> 2;          // 0..63 (+64 for i=1)
    const int cg   = (tid & 3) << 3;    // granule offset in halves: 0,8,16,24

    const __half* Agp = A  + (size_t)(bm + crow) * Kdim + cg;
    const __half* Bgp = Bt + (size_t)(bn + crow) * Kdim + cg;
    const size_t r64 = (size_t)64 * Kdim;

    float acc[2][8][4];
    #pragma unroll
    for (int mt = 0; mt < 2; mt++)
        #pragma unroll
        for (int nt = 0; nt < 8; nt++)
            #pragma unroll
            for (int c = 0; c < 4; c++) acc[mt][nt][c] = 0.f;

    const int ktiles = Kdim >> 5;   // BK = 32 halves

    // prologue: stage 0 (k0 = 0)
    cp16(&As[0][crow * SA + cg],        Agp);
    cp16(&As[0][(crow + 64) * SA + cg], Agp + r64);
    cp16(&Bs[0][crow * SA + cg],        Bgp);
    cp16(&Bs[0][(crow + 64) * SA + cg], Bgp + r64);
    CP_COMMIT();

    for (int t = 0; t < ktiles; t++) {
        const int s = t & 1;
        if (t + 1 < ktiles) {
            const int nx = s ^ 1;
            const int k0 = (t + 1) << 5;
            cp16(&As[nx][crow * SA + cg],        Agp + k0);
            cp16(&As[nx][(crow + 64) * SA + cg], Agp + r64 + k0);
            cp16(&Bs[nx][crow * SA + cg],        Bgp + k0);
            cp16(&Bs[nx][(crow + 64) * SA + cg], Bgp + r64 + k0);
        }
        CP_COMMIT();
        CP_WAIT1();                 // stage s complete (newest group may fly)
        __syncthreads();

        const unsigned* as = (const unsigned*)As[s];   // row stride 20 b32
        const unsigned* bs = (const unsigned*)Bs[s];
        #pragma unroll
        for (int ks = 0; ks < 2; ks++) {
            const int kb = ks * 8;   // b32 offset within row
            unsigned afr[2][4];
            #pragma unroll
            for (int mt = 0; mt < 2; mt++) {
                const int row = wm + mt * 16 + gid;
                afr[mt][0] = as[row * 20 + kb + tig];
                afr[mt][1] = as[(row + 8) * 20 + kb + tig];
                afr[mt][2] = as[row * 20 + kb + tig + 4];
                afr[mt][3] = as[(row + 8) * 20 + kb + tig + 4];
            }
            unsigned bfr[8][2];
            #pragma unroll
            for (int nt = 0; nt < 8; nt++) {
                const int col = wn + nt * 8 + gid;
                bfr[nt][0] = bs[col * 20 + kb + tig];
                bfr[nt][1] = bs[col * 20 + kb + tig + 4];
            }
            #pragma unroll
            for (int mt = 0; mt < 2; mt++)
                #pragma unroll
                for (int nt = 0; nt < 8; nt++)
                    mma_f16(acc[mt][nt],
                            afr[mt][0], afr[mt][1], afr[mt][2], afr[mt][3],
                            bfr[nt][0], bfr[nt][1]);
        }
        __syncthreads();            // protect stage s before refill
    }

    // epilogue: bias + fp32 store
    #pragma unroll
    for (int mt = 0; mt < 2; mt++) {
        const int row0 = bm + wm + mt * 16 + gid;
        #pragma unroll
        for (int nt = 0; nt < 8; nt++) {
            const int col = bn + wn + nt * 8 + 2 * tig;
            const float b0 = bias[col], b1 = bias[col + 1];
            float2 o0, o1;
            o0.x = acc[mt][nt][0] + b0;
            o0.y = acc[mt][nt][1] + b1;
            o1.x = acc[mt][nt][2] + b0;
            o1.y = acc[mt][nt][3] + b1;
            *(float2*)&C[(size_t)row0 * Ndim + col]       = o0;
            *(float2*)&C[(size_t)(row0 + 8) * Ndim + col] = o1;
        }
    }
}

// ---------------- fused attention (fp32 math, half output) ----------------
__global__ __launch_bounds__(256) void attn_kernel(
    const float* __restrict__ q,      // (B,N,D)
    const float* __restrict__ kv,     // (B,N,2D)
    const float* __restrict__ kvsim,  // (B,N,M,2D)
    __half* __restrict__ outa)        // (B,N,D) half
{
    extern __shared__ float sm[];
    float* qs = sm;               // 64*65
    float* ks = qs + 64 * 65;
    float* ps = ks + 64 * 65;
    float* vs = ps + 64 * 65;     // 64*64

    const int tid = threadIdx.x;
    const int n0 = blockIdx.x * 64;
    const int h  = blockIdx.y;
    const int b  = blockIdx.z;
    const float scale = kSCALE;

    for (int i = tid; i < 1024; i += 256) {
        int row = i >> 4;
        int c4  = (i & 15) << 2;
        float4 v = *(const float4*)&q[(size_t)(b * N_ + n0 + row) * D_ + h * DH + c4];
        float* dst = &qs[row * 65 + c4];
        dst[0] = v.x * scale; dst[1] = v.y * scale;
        dst[2] = v.z * scale; dst[3] = v.w * scale;
    }

    const int qi = tid >> 2;
    const int r  = tid & 3;
    const int tq = tid >> 4;
    const int tk = tid & 15;

    float m_i = -1e30f, l_i = 0.f;
    float acc[16];
    #pragma unroll
    for (int c = 0; c < 16; c++) acc[c] = 0.f;

    for (int kt = 0; kt < 8; kt++) {
        __syncthreads();
        for (int i = tid; i < 1024; i += 256) {
            int row = i >> 4;
            int c4  = (i & 15) << 2;
            size_t gbase = (size_t)(b * N_ + kt * 64 + row) * (2 * D_) + h * DH + c4;
            float4 kk = *(const float4*)&kv[gbase];
            float* kd = &ks[row * 65 + c4];
            kd[0] = kk.x; kd[1] = kk.y; kd[2] = kk.z; kd[3] = kk.w;
            *(float4*)&vs[row * 64 + c4] = *(const float4*)&kv[gbase + D_];
        }
        __syncthreads();

        float sc[4][4];
        #pragma unroll
        for (int i = 0; i < 4; i++)
            #pragma unroll
            for (int j = 0; j < 4; j++) sc[i][j] = 0.f;
        #pragma unroll 4
        for (int d = 0; d < 64; d++) {
            float qd[4], kd[4];
            #pragma unroll
            for (int i = 0; i < 4; i++) qd[i] = qs[(tq * 4 + i) * 65 + d];
            #pragma unroll
            for (int j = 0; j < 4; j++) kd[j] = ks[(tk * 4 + j) * 65 + d];
            #pragma unroll
            for (int i = 0; i < 4; i++)
                #pragma unroll
                for (int j = 0; j < 4; j++)
                    sc[i][j] += qd[i] * kd[j];
        }
        #pragma unroll
        for (int i = 0; i < 4; i++)
            #pragma unroll
            for (int j = 0; j < 4; j++)
                ps[(tq * 4 + i) * 65 + tk * 4 + j] = sc[i][j];
        __syncthreads();

        float pv[16];
        float tmax = -1e30f;
        #pragma unroll
        for (int j = 0; j < 16; j++) {
            pv[j] = ps[qi * 65 + 4 * j + r];
            tmax = fmaxf(tmax, pv[j]);
        }
        tmax = fmaxf(tmax, __shfl_xor_sync(0xffffffffu, tmax, 1));
        tmax = fmaxf(tmax, __shfl_xor_sync(0xffffffffu, tmax, 2));
        float nm   = fmaxf(m_i, tmax);
        float corr = __expf(m_i - nm);
        float psum = 0.f;
        #pragma unroll
        for (int j = 0; j < 16; j++) { pv[j] = __expf(pv[j] - nm); psum += pv[j]; }
        psum += __shfl_xor_sync(0xffffffffu, psum, 1);
        psum += __shfl_xor_sync(0xffffffffu, psum, 2);
        l_i = l_i * corr + psum;
        m_i = nm;
        #pragma unroll
        for (int c = 0; c < 16; c++) acc[c] *= corr;
        #pragma unroll
        for (int j = 0; j < 16; j++) ps[qi * 65 + 4 * j + r] = pv[j];
        __syncwarp();

        for (int kj = 0; kj < 64; kj++) {
            float p = ps[qi * 65 + kj];
            const float* vp = &vs[kj * 64 + r * 16];
            #pragma unroll
            for (int c4 = 0; c4 < 4; c4++) {
                float4 v = *(const float4*)&vp[c4 * 4];
                acc[c4 * 4 + 0] += p * v.x;
                acc[c4 * 4 + 1] += p * v.y;
                acc[c4 * 4 + 2] += p * v.z;
                acc[c4 * 4 + 3] += p * v.w;
            }
        }
    }

    {
        size_t simbase = (size_t)(b * N_ + n0 + qi) * M_ * (2 * D_) + h * DH;
        float sc2[2];
        #pragma unroll
        for (int e = 0; e < 2; e++) {
            int m = r * 2 + e;
            const float* kp = &kvsim[simbase + (size_t)m * (2 * D_)];
            float s = 0.f;
            #pragma unroll 4
            for (int d4 = 0; d4 < 16; d4++) {
                float4 kk = *(const float4*)&kp[d4 * 4];
                const float* qp = &qs[qi * 65 + d4 * 4];
                s += qp[0] * kk.x + qp[1] * kk.y + qp[2] * kk.z + qp[3] * kk.w;
            }
            sc2[e] = s;
        }
        float tmax = fmaxf(sc2[0], sc2[1]);
        tmax = fmaxf(tmax, __shfl_xor_sync(0xffffffffu, tmax, 1));
        tmax = fmaxf(tmax, __shfl_xor_sync(0xffffffffu, tmax, 2));
        float nm   = fmaxf(m_i, tmax);
        float corr = __expf(m_i - nm);
        float p0 = __expf(sc2[0] - nm);
        float p1 = __expf(sc2[1] - nm);
        float psum = p0 + p1;
        psum += __shfl_xor_sync(0xffffffffu, psum, 1);
        psum += __shfl_xor_sync(0xffffffffu, psum, 2);
        l_i = l_i * corr + psum;
        #pragma unroll
        for (int c = 0; c < 16; c++) acc[c] *= corr;

        #pragma unroll
        for (int s4 = 0; s4 < 4; s4++) {
            float pa = __shfl_sync(0xffffffffu, p0, s4, 4);
            float pb = __shfl_sync(0xffffffffu, p1, s4, 4);
            const float* va = &kvsim[simbase + (size_t)(2 * s4) * (2 * D_) + D_ + r * 16];
            const float* vb = va + 2 * D_;
            #pragma unroll
            for (int c4 = 0; c4 < 4; c4++) {
                float4 v = *(const float4*)&va[c4 * 4];
                float4 w = *(const float4*)&vb[c4 * 4];
                acc[c4 * 4 + 0] += pa * v.x + pb * w.x;
                acc[c4 * 4 + 1] += pa * v.y + pb * w.y;
                acc[c4 * 4 + 2] += pa * v.z + pb * w.z;
                acc[c4 * 4 + 3] += pa * v.w + pb * w.w;
            }
        }
    }

    // write normalized output as half (feeds final fp16 GEMM)
    float inv = 1.f / l_i;
    __half2* op = (__half2*)&outa[(size_t)(b * N_ + n0 + qi) * D_ + h * DH + r * 16];
    #pragma unroll
    for (int c4 = 0; c4 < 4; c4++) {
        op[c4 * 2 + 0] = __floats2half2_rn(acc[c4 * 4 + 0] * inv, acc[c4 * 4 + 1] * inv);
        op[c4 * 2 + 1] = __floats2half2_rn(acc[c4 * 4 + 2] * inv, acc[c4 * 4 + 3] * inv);
    }
}

// ---------------- launch ----------------
extern "C" void kernel_launch(void* const* d_in, const int* in_sizes, int n_in,
                              void* d_out, int out_size)
{
    const float* x   = (const float*)d_in[0];
    const float* sim = (const float*)d_in[1];
    const float* Wq  = (const float*)d_in[2];
    const float* bq  = (const float*)d_in[3];
    const float* Wkv = (const float*)d_in[4];
    const float* bkv = (const float*)d_in[5];
    const float* Wp  = (const float*)d_in[6];
    const float* bp  = (const float*)d_in[7];
    float* out = (float*)d_out;

    float  *q, *kvb, *kvs;
    __half *att, *xh, *simh, *wqt, *wkvt, *wpt;
    cudaGetSymbolAddress((void**)&q,    g_q);
    cudaGetSymbolAddress((void**)&kvb,  g_kv);
    cudaGetSymbolAddress((void**)&kvs,  g_kvsim);
    cudaGetSymbolAddress((void**)&att,  g_att);
    cudaGetSymbolAddress((void**)&xh,   g_xh);
    cudaGetSymbolAddress((void**)&simh, g_simh);
    cudaGetSymbolAddress((void**)&wqt,  g_wqt);
    cudaGetSymbolAddress((void**)&wkvt, g_wkvt);
    cudaGetSymbolAddress((void**)&wpt,  g_wpt);

    const int ATTN_SMEM = (3 * 64 * 65 + 64 * 64) * sizeof(float); // 66304
    cudaFuncSetAttribute(attn_kernel,
                         cudaFuncAttributeMaxDynamicSharedMemorySize, ATTN_SMEM);

    const int BN  = B_ * N_;          // 8192
    const int BNM = B_ * N_ * M_;     // 65536

    // prep: half conversions + weight transposes
    f2h_kernel<<<(BN * D_ / 4 + 255) / 256, 256>>>(x, xh, BN * D_ / 4);
    f2h_kernel<<<(BNM * D_ / 4 + 255) / 256, 256>>>(sim, simh, BNM * D_ / 4);
    transpose_h_kernel<<<dim3(D_ / 32, D_ / 32), dim3(32, 8)>>>(Wq,  wqt,  D_, D_);
    transpose_h_kernel<<<dim3(2 * D_ / 32, D_ / 32), dim3(32, 8)>>>(Wkv, wkvt, D_, 2 * D_);
    transpose_h_kernel<<<dim3(D_ / 32, D_ / 32), dim3(32, 8)>>>(Wp,  wpt,  D_, D_);

    // fp16 tensor-core GEMMs
    hgemm_bias<<<dim3(D_ / 128, BN / 128), 256>>>(xh, wqt, bq, q, BN, D_, D_);
    hgemm_bias<<<dim3(2 * D_ / 128, BN / 128), 256>>>(xh, wkvt, bkv, kvb, BN, 2 * D_, D_);
    hgemm_bias<<<dim3(2 * D_ / 128, BNM / 128), 256>>>(simh, wkvt, bkv, kvs, BNM, 2 * D_, D_);
    attn_kernel<<<dim3(N_ / 64, H_, B_), 256, ATTN_SMEM>>>(q, kvb, kvs, att);
    hgemm_bias<<<dim3(D_ / 128, BN / 128), 256>>>(att, wpt, bp, out, BN, D_, D_);
}

// round 6
// speedup vs baseline: 2.8873x; 1.0053x over previous
#include <cuda_runtime.h>
#include <cuda_fp16.h>
#include <cstdint>
#include <cstdio>

#define B_  16
#define N_  512
#define M_  8
#define D_  768
#define H_  12
#define DH  64
__device__ __constant__ float kSCALE = 0.125f; // 64^{-0.5}

// ---------------- scratch (device globals; no cudaMalloc allowed) ----------------
__device__ float  g_q    [B_ * N_ * D_];              // (B,N,D) fp32
__device__ float  g_kv   [B_ * N_ * 2 * D_];          // (B,N,2D) fp32
__device__ __half g_kvsimh[B_ * N_ * M_ * 2 * D_];    // (B,N,M,2D) half (201 MB)
__device__ __half g_att  [B_ * N_ * D_];              // (B,N,D) half
__device__ __half g_xh   [B_ * N_ * D_];              // x in half
__device__ __half g_simh [B_ * N_ * M_ * D_];         // sim in half
__device__ __half g_wqt  [D_ * D_];                   // Wq^T  [N][K] half
__device__ __half g_wkvt [2 * D_ * D_];               // Wkv^T [2D][D] half
__device__ __half g_wpt  [D_ * D_];                   // Wp^T half

// ---------------- helpers ----------------
__device__ __forceinline__ void cp16(void* smem_dst, const void* gmem_src) {
    unsigned s = (unsigned)__cvta_generic_to_shared(smem_dst);
    asm volatile("cp.async.cg.shared.global [%0], [%1], 16;\n"
                 :: "r"(s), "l"(gmem_src));
}
#define CP_COMMIT() asm volatile("cp.async.commit_group;\n" ::: "memory")
#define CP_WAIT2()  asm volatile("cp.async.wait_group 2;\n" ::: "memory")

__device__ __forceinline__ void mma_f16(float d[4],
                                        unsigned a0, unsigned a1, unsigned a2, unsigned a3,
                                        unsigned b0, unsigned b1)
{
    asm volatile(
        "mma.sync.aligned.m16n8k16.row.col.f32.f16.f16.f32 "
        "{%0,%1,%2,%3}, {%4,%5,%6,%7}, {%8,%9}, {%0,%1,%2,%3};\n"
        : "+f"(d[0]), "+f"(d[1]), "+f"(d[2]), "+f"(d[3])
        : "r"(a0), "r"(a1), "r"(a2), "r"(a3), "r"(b0), "r"(b1));
}

__device__ __forceinline__ void ldm_x4(unsigned r[4], const __half* p) {
    unsigned a = (unsigned)__cvta_generic_to_shared(p);
    asm volatile("ldmatrix.sync.aligned.m8n8.x4.shared.b16 {%0,%1,%2,%3}, [%4];"
                 : "=r"(r[0]), "=r"(r[1]), "=r"(r[2]), "=r"(r[3]) : "r"(a));
}

// ---------------- prep kernels ----------------
__global__ void f2h_kernel(const float* __restrict__ in,
                           __half* __restrict__ out, int n4) {
    int i = blockIdx.x * blockDim.x + threadIdx.x;
    if (i < n4) {
        float4 v = ((const float4*)in)[i];
        ((__half2*)out)[2 * i]     = __floats2half2_rn(v.x, v.y);
        ((__half2*)out)[2 * i + 1] = __floats2half2_rn(v.z, v.w);
    }
}

// Wt[n][k] = half(W[k][n]); K rows, N cols; K,N multiples of 32
__global__ void transpose_h_kernel(const float* __restrict__ W,
                                   __half* __restrict__ Wt, int K, int N) {
    __shared__ float t[32][33];
    int k0 = blockIdx.y * 32, n0 = blockIdx.x * 32;
    int x = threadIdx.x, y = threadIdx.y;          // block (32,8)
    #pragma unroll
    for (int i = 0; i < 32; i += 8)
        t[y + i][x] = W[(size_t)(k0 + y + i) * N + n0 + x];
    __syncthreads();
    #pragma unroll
    for (int i = 0; i < 32; i += 8)
        Wt[(size_t)(n0 + y + i) * K + k0 + x] = __float2half_rn(t[x][y + i]);
}

// ---------------- fp16 GEMM + bias: 256x128 tile, 64x64 warp tile, ldmatrix ----
// C[M,N] = A[M,K] @ Bt[N,K]^T + bias[N]   (A, Bt half; bias fp32; C = OutT)
// 256 threads (8 warps, 4x2), BK=32 halves, 3-stage cp.async ring (dyn smem).
// As/Bs rows: stride 40 halves -> ldmatrix phases conflict-free (banks 20r%32).
// Requires M%256==0, N%128==0, K%32==0.
#define SAH  40
#define ABYT (256 * SAH * 2)              // 20480 B per stage
#define BBYT (128 * SAH * 2)              // 10240 B per stage
#define STG  (ABYT + BBYT)                // 30720 B
#define GEMM_SMEM (3 * STG)               // 92160 B

template <typename OutT>
__global__ __launch_bounds__(256, 1) void hgemm_bias(
    const __half* __restrict__ A, const __half* __restrict__ Bt,
    const float* __restrict__ bias, OutT* __restrict__ C,
    int Mdim, int Ndim, int Kdim)
{
    extern __shared__ __half smem[];

    const int tid  = threadIdx.x;
    const int warp = tid >> 5;
    const int lane = tid & 31;
    const int gid  = lane >> 2;
    const int tig  = lane & 3;
    const int wm   = (warp >> 1) * 64;   // 0,64,128,192
    const int wn   = (warp & 1)  * 64;   // 0,64
    const int bm   = blockIdx.y * 256;
    const int bn   = blockIdx.x * 128;

    // cp.async mapping: rows of 32 halves = 4 granules of 16B
    const int crow = tid >> 2;          // 0..63
    const int cg   = (tid & 3) << 3;    // half offset 0,8,16,24
    const __half* Agp = A  + (size_t)(bm + crow) * Kdim + cg;
    const __half* Bgp = Bt + (size_t)(bn + crow) * Kdim + cg;
    const size_t r64 = (size_t)64 * Kdim;

    const int ktiles = Kdim >> 5;

    auto load_stage = [&](int s, int t) {
        __half* as = smem + s * (STG / 2);
        __half* bs = as + ABYT / 2;
        const int k0 = t << 5;
        #pragma unroll
        for (int i = 0; i < 4; i++)
            cp16(&as[(crow + i * 64) * SAH + cg], Agp + i * r64 + k0);
        #pragma unroll
        for (int i = 0; i < 2; i++)
            cp16(&bs[(crow + i * 64) * SAH + cg], Bgp + i * r64 + k0);
    };

    float acc[4][8][4];
    #pragma unroll
    for (int mt = 0; mt < 4; mt++)
        #pragma unroll
        for (int nt = 0; nt < 8; nt++)
            #pragma unroll
            for (int c = 0; c < 4; c++) acc[mt][nt][c] = 0.f;

    load_stage(0, 0); CP_COMMIT();
    if (ktiles > 1) load_stage(1, 1);
    CP_COMMIT();

    // ldmatrix lane offsets (in halves, within stage)
    const int a_off = (wm + (lane & 15)) * SAH + ((lane >> 4) << 3);
    const int b_off = (wn + ((lane >> 4) << 3) + (lane & 7)) * SAH
                    + (((lane >> 3) & 1) << 3);

    for (int t = 0; t < ktiles; t++) {
        if (t + 2 < ktiles) load_stage((t + 2) % 3, t + 2);
        CP_COMMIT();
        CP_WAIT2();
        __syncthreads();

        const __half* as = smem + (t % 3) * (STG / 2);
        const __half* bs = as + ABYT / 2;

        #pragma unroll
        for (int ks = 0; ks < 2; ks++) {
            const int kh = ks << 4;
            unsigned afr[4][4], bfr[4][4];
            #pragma unroll
            for (int mt = 0; mt < 4; mt++)
                ldm_x4(afr[mt], as + a_off + mt * 16 * SAH + kh);
            #pragma unroll
            for (int np = 0; np < 4; np++)
                ldm_x4(bfr[np], bs + b_off + np * 16 * SAH + kh);
            #pragma unroll
            for (int mt = 0; mt < 4; mt++)
                #pragma unroll
                for (int nt = 0; nt < 8; nt++) {
                    const unsigned* bp = bfr[nt >> 1];
                    const int e = (nt & 1) << 1;   // 0 or 2
                    mma_f16(acc[mt][nt],
                            afr[mt][0], afr[mt][1], afr[mt][2], afr[mt][3],
                            bp[e], bp[e + 1]);
                }
        }
        __syncthreads();
    }

    // epilogue: bias + store
    #pragma unroll
    for (int mt = 0; mt < 4; mt++) {
        const int row0 = bm + wm + mt * 16 + gid;
        #pragma unroll
        for (int nt = 0; nt < 8; nt++) {
            const int col = bn + wn + nt * 8 + 2 * tig;
            const float b0 = bias[col], b1 = bias[col + 1];
            if constexpr (sizeof(OutT) == 4) {
                float2 o0, o1;
                o0.x = acc[mt][nt][0] + b0; o0.y = acc[mt][nt][1] + b1;
                o1.x = acc[mt][nt][2] + b0; o1.y = acc[mt][nt][3] + b1;
                *(float2*)&C[(size_t)row0 * Ndim + col]       = o0;
                *(float2*)&C[(size_t)(row0 + 8) * Ndim + col] = o1;
            } else {
                *(__half2*)&C[(size_t)row0 * Ndim + col] =
                    __floats2half2_rn(acc[mt][nt][0] + b0, acc[mt][nt][1] + b1);
                *(__half2*)&C[(size_t)(row0 + 8) * Ndim + col] =
                    __floats2half2_rn(acc[mt][nt][2] + b0, acc[mt][nt][3] + b1);
            }
        }
    }
}

// ---------------- fused attention (fp32 math; kv fp32, kvsim half, out half) ----
__global__ __launch_bounds__(256) void attn_kernel(
    const float*  __restrict__ q,       // (B,N,D)
    const float*  __restrict__ kv,      // (B,N,2D)
    const __half* __restrict__ kvsimh,  // (B,N,M,2D) half
    __half* __restrict__ outa)          // (B,N,D) half
{
    extern __shared__ float sm[];
    float* qs = sm;               // 64*65
    float* ks = qs + 64 * 65;
    float* ps = ks + 64 * 65;
    float* vs = ps + 64 * 65;     // 64*64

    const int tid = threadIdx.x;
    const int n0 = blockIdx.x * 64;
    const int h  = blockIdx.y;
    const int b  = blockIdx.z;
    const float scale = kSCALE;

    for (int i = tid; i < 1024; i += 256) {
        int row = i >> 4;
        int c4  = (i & 15) << 2;
        float4 v = *(const float4*)&q[(size_t)(b * N_ + n0 + row) * D_ + h * DH + c4];
        float* dst = &qs[row * 65 + c4];
        dst[0] = v.x * scale; dst[1] = v.y * scale;
        dst[2] = v.z * scale; dst[3] = v.w * scale;
    }

    const int qi = tid >> 2;
    const int r  = tid & 3;
    const int tq = tid >> 4;
    const int tk = tid & 15;

    float m_i = -1e30f, l_i = 0.f;
    float acc[16];
    #pragma unroll
    for (int c = 0; c < 16; c++) acc[c] = 0.f;

    for (int kt = 0; kt < 8; kt++) {
        __syncthreads();
        for (int i = tid; i < 1024; i += 256) {
            int row = i >> 4;
            int c4  = (i & 15) << 2;
            size_t gbase = (size_t)(b * N_ + kt * 64 + row) * (2 * D_) + h * DH + c4;
            float4 kk = *(const float4*)&kv[gbase];
            float* kd = &ks[row * 65 + c4];
            kd[0] = kk.x; kd[1] = kk.y; kd[2] = kk.z; kd[3] = kk.w;
            *(float4*)&vs[row * 64 + c4] = *(const float4*)&kv[gbase + D_];
        }
        __syncthreads();

        float sc[4][4];
        #pragma unroll
        for (int i = 0; i < 4; i++)
            #pragma unroll
            for (int j = 0; j < 4; j++) sc[i][j] = 0.f;
        #pragma unroll 4
        for (int d = 0; d < 64; d++) {
            float qd[4], kd[4];
            #pragma unroll
            for (int i = 0; i < 4; i++) qd[i] = qs[(tq * 4 + i) * 65 + d];
            #pragma unroll
            for (int j = 0; j < 4; j++) kd[j] = ks[(tk * 4 + j) * 65 + d];
            #pragma unroll
            for (int i = 0; i < 4; i++)
                #pragma unroll
                for (int j = 0; j < 4; j++)
                    sc[i][j] += qd[i] * kd[j];
        }
        #pragma unroll
        for (int i = 0; i < 4; i++)
            #pragma unroll
            for (int j = 0; j < 4; j++)
                ps[(tq * 4 + i) * 65 + tk * 4 + j] = sc[i][j];
        __syncthreads();

        float pv[16];
        float tmax = -1e30f;
        #pragma unroll
        for (int j = 0; j < 16; j++) {
            pv[j] = ps[qi * 65 + 4 * j + r];
            tmax = fmaxf(tmax, pv[j]);
        }
        tmax = fmaxf(tmax, __shfl_xor_sync(0xffffffffu, tmax, 1));
        tmax = fmaxf(tmax, __shfl_xor_sync(0xffffffffu, tmax, 2));
        float nm   = fmaxf(m_i, tmax);
        float corr = __expf(m_i - nm);
        float psum = 0.f;
        #pragma unroll
        for (int j = 0; j < 16; j++) { pv[j] = __expf(pv[j] - nm); psum += pv[j]; }
        psum += __shfl_xor_sync(0xffffffffu, psum, 1);
        psum += __shfl_xor_sync(0xffffffffu, psum, 2);
        l_i = l_i * corr + psum;
        m_i = nm;
        #pragma unroll
        for (int c = 0; c < 16; c++) acc[c] *= corr;
        #pragma unroll
        for (int j = 0; j < 16; j++) ps[qi * 65 + 4 * j + r] = pv[j];
        __syncwarp();

        for (int kj = 0; kj < 64; kj++) {
            float p = ps[qi * 65 + kj];
            const float* vp = &vs[kj * 64 + r * 16];
            #pragma unroll
            for (int c4 = 0; c4 < 4; c4++) {
                float4 v = *(const float4*)&vp[c4 * 4];
                acc[c4 * 4 + 0] += p * v.x;
                acc[c4 * 4 + 1] += p * v.y;
                acc[c4 * 4 + 2] += p * v.z;
                acc[c4 * 4 + 3] += p * v.w;
            }
        }
    }

    // ---- sim keys (half storage) ----
    {
        size_t simbase = (size_t)(b * N_ + n0 + qi) * M_ * (2 * D_) + h * DH;
        float sc2[2];
        #pragma unroll
        for (int e = 0; e < 2; e++) {
            int m = r * 2 + e;
            const float4* kp4 = (const float4*)&kvsimh[simbase + (size_t)m * (2 * D_)];
            float s = 0.f;
            #pragma unroll
            for (int g = 0; g < 8; g++) {           // 8 halves per float4
                float4 raw = kp4[g];
                const __half2* hp = (const __half2*)&raw;
                const float* qp = &qs[qi * 65 + g * 8];
                #pragma unroll
                for (int j = 0; j < 4; j++) {
                    float2 f = __half22float2(hp[j]);
                    s += qp[2 * j] * f.x + qp[2 * j + 1] * f.y;
                }
            }
            sc2[e] = s;
        }
        float tmax = fmaxf(sc2[0], sc2[1]);
        tmax = fmaxf(tmax, __shfl_xor_sync(0xffffffffu, tmax, 1));
        tmax = fmaxf(tmax, __shfl_xor_sync(0xffffffffu, tmax, 2));
        float nm   = fmaxf(m_i, tmax);
        float corr = __expf(m_i - nm);
        float p0 = __expf(sc2[0] - nm);
        float p1 = __expf(sc2[1] - nm);
        float psum = p0 + p1;
        psum += __shfl_xor_sync(0xffffffffu, psum, 1);
        psum += __shfl_xor_sync(0xffffffffu, psum, 2);
        l_i = l_i * corr + psum;
        #pragma unroll
        for (int c = 0; c < 16; c++) acc[c] *= corr;

        #pragma unroll
        for (int s4 = 0; s4 < 4; s4++) {
            float pa = __shfl_sync(0xffffffffu, p0, s4, 4);
            float pb = __shfl_sync(0xffffffffu, p1, s4, 4);
            const __half* va = &kvsimh[simbase + (size_t)(2 * s4) * (2 * D_) + D_ + r * 16];
            const __half* vb = va + 2 * D_;
            #pragma unroll
            for (int half4 = 0; half4 < 2; half4++) {  // two float4 = 8 halves each
                float4 ra = ((const float4*)va)[half4];
                float4 rb = ((const float4*)vb)[half4];
                const __half2* ha = (const __half2*)&ra;
                const __half2* hb = (const __half2*)&rb;
                #pragma unroll
                for (int j = 0; j < 4; j++) {
                    float2 fa = __half22float2(ha[j]);
                    float2 fb = __half22float2(hb[j]);
                    int c = half4 * 8 + 2 * j;
                    acc[c + 0] += pa * fa.x + pb * fb.x;
                    acc[c + 1] += pa * fa.y + pb * fb.y;
                }
            }
        }
    }

    // write normalized output as half (feeds final fp16 GEMM)
    float inv = 1.f / l_i;
    __half2* op = (__half2*)&outa[(size_t)(b * N_ + n0 + qi) * D_ + h * DH + r * 16];
    #pragma unroll
    for (int c4 = 0; c4 < 4; c4++) {
        op[c4 * 2 + 0] = __floats2half2_rn(acc[c4 * 4 + 0] * inv, acc[c4 * 4 + 1] * inv);
        op[c4 * 2 + 1] = __floats2half2_rn(acc[c4 * 4 + 2] * inv, acc[c4 * 4 + 3] * inv);
    }
}

// ---------------- launch ----------------
extern "C" void kernel_launch(void* const* d_in, const int* in_sizes, int n_in,
                              void* d_out, int out_size)
{
    const float* x   = (const float*)d_in[0];
    const float* sim = (const float*)d_in[1];
    const float* Wq  = (const float*)d_in[2];
    const float* bq  = (const float*)d_in[3];
    const float* Wkv = (const float*)d_in[4];
    const float* bkv = (const float*)d_in[5];
    const float* Wp  = (const float*)d_in[6];
    const float* bp  = (const float*)d_in[7];
    float* out = (float*)d_out;

    float  *q, *kvb;
    __half *kvsh, *att, *xh, *simh, *wqt, *wkvt, *wpt;
    cudaGetSymbolAddress((void**)&q,    g_q);
    cudaGetSymbolAddress((void**)&kvb,  g_kv);
    cudaGetSymbolAddress((void**)&kvsh, g_kvsimh);
    cudaGetSymbolAddress((void**)&att,  g_att);
    cudaGetSymbolAddress((void**)&xh,   g_xh);
    cudaGetSymbolAddress((void**)&simh, g_simh);
    cudaGetSymbolAddress((void**)&wqt,  g_wqt);
    cudaGetSymbolAddress((void**)&wkvt, g_wkvt);
    cudaGetSymbolAddress((void**)&wpt,  g_wpt);

    const int ATTN_SMEM = (3 * 64 * 65 + 64 * 64) * sizeof(float); // 66304
    cudaFuncSetAttribute(attn_kernel,
                         cudaFuncAttributeMaxDynamicSharedMemorySize, ATTN_SMEM);
    cudaFuncSetAttribute(hgemm_bias<float>,
                         cudaFuncAttributeMaxDynamicSharedMemorySize, GEMM_SMEM);
    cudaFuncSetAttribute(hgemm_bias<__half>,
                         cudaFuncAttributeMaxDynamicSharedMemorySize, GEMM_SMEM);

    const int BN  = B_ * N_;          // 8192
    const int BNM = B_ * N_ * M_;     // 65536

    // prep: half conversions + weight transposes
    f2h_kernel<<<(BN * D_ / 4 + 255) / 256, 256>>>(x, xh, BN * D_ / 4);
    f2h_kernel<<<(BNM * D_ / 4 + 255) / 256, 256>>>(sim, simh, BNM * D_ / 4);
    transpose_h_kernel<<<dim3(D_ / 32, D_ / 32), dim3(32, 8)>>>(Wq,  wqt,  D_, D_);
    transpose_h_kernel<<<dim3(2 * D_ / 32, D_ / 32), dim3(32, 8)>>>(Wkv, wkvt, D_, 2 * D_);
    transpose_h_kernel<<<dim3(D_ / 32, D_ / 32), dim3(32, 8)>>>(Wp,  wpt,  D_, D_);

    // fp16 tensor-core GEMMs (256x128 tiles)
    hgemm_bias<float><<<dim3(D_ / 128, BN / 256), 256, GEMM_SMEM>>>(
        xh, wqt, bq, q, BN, D_, D_);
    hgemm_bias<float><<<dim3(2 * D_ / 128, BN / 256), 256, GEMM_SMEM>>>(
        xh, wkvt, bkv, kvb, BN, 2 * D_, D_);
    hgemm_bias<__half><<<dim3(2 * D_ / 128, BNM / 256), 256, GEMM_SMEM>>>(
        simh, wkvt, bkv, kvsh, BNM, 2 * D_, D_);
    attn_kernel<<<dim3(N_ / 64, H_, B_), 256, ATTN_SMEM>>>(q, kvb, kvsh, att);
    hgemm_bias<float><<<dim3(D_ / 128, BN / 256), 256, GEMM_SMEM>>>(
        att, wpt, bp, out, BN, D_, D_);
}

// round 7
// speedup vs baseline: 3.3701x; 1.1672x over previous
#include <cuda_runtime.h>
#include <cuda_fp16.h>
#include <cstdint>
#include <cstdio>

#define B_  16
#define N_  512
#define M_  8
#define D_  768
#define H_  12
#define DH  64
__device__ __constant__ float kSCALE = 0.125f; // 64^{-0.5}

// ---------------- scratch (device globals; no cudaMalloc allowed) ----------------
__device__ __half g_qh   [B_ * N_ * D_];             // q (B,N,D) half
__device__ float  g_kv   [B_ * N_ * 2 * D_];         // (B,N,2D) fp32
__device__ __half g_att  [B_ * N_ * D_];             // out_self + out_sim (half)
__device__ __half g_xh   [B_ * N_ * D_];             // x half
__device__ __half g_simh [B_ * N_ * M_ * D_];        // sim half (100 MB)
__device__ __half g_t    [B_ * N_ * H_ * D_];        // t[bn][h][768] half (151 MB)
__device__ __half g_s    [H_ * B_ * N_ * D_];        // s[h][bn][768] half (151 MB)
__device__ float  g_ls   [B_ * H_ * N_ * M_];        // raw sim logits (25 MB)
__device__ float  g_w    [H_ * B_ * N_ * M_];        // normalized sim weights (25 MB)
__device__ float  g_asum [H_ * B_ * N_];             // sum of sim weights per (h,bn)
__device__ __half g_wqt  [D_ * D_];                  // Wq^T  [N][K]
__device__ __half g_wkvt [2 * D_ * D_];              // Wkv^T [2D][D]
__device__ __half g_wkvh [D_ * 2 * D_];              // Wkv (row-major) half
__device__ __half g_wpt  [D_ * D_];                  // Wp^T
__device__ float  g_zeros[D_];                       // zero bias (zero-initialized)

// ---------------- helpers ----------------
__device__ __forceinline__ void cp16(void* smem_dst, const void* gmem_src) {
    unsigned s = (unsigned)__cvta_generic_to_shared(smem_dst);
    asm volatile("cp.async.cg.shared.global [%0], [%1], 16;\n"
                 :: "r"(s), "l"(gmem_src));
}
#define CP_COMMIT() asm volatile("cp.async.commit_group;\n" ::: "memory")
#define CP_WAIT2()  asm volatile("cp.async.wait_group 2;\n" ::: "memory")

__device__ __forceinline__ void mma_f16(float d[4],
                                        unsigned a0, unsigned a1, unsigned a2, unsigned a3,
                                        unsigned b0, unsigned b1)
{
    asm volatile(
        "mma.sync.aligned.m16n8k16.row.col.f32.f16.f16.f32 "
        "{%0,%1,%2,%3}, {%4,%5,%6,%7}, {%8,%9}, {%0,%1,%2,%3};\n"
        : "+f"(d[0]), "+f"(d[1]), "+f"(d[2]), "+f"(d[3])
        : "r"(a0), "r"(a1), "r"(a2), "r"(a3), "r"(b0), "r"(b1));
}
__device__ __forceinline__ void ldm_x4(unsigned r[4], const __half* p) {
    unsigned a = (unsigned)__cvta_generic_to_shared(p);
    asm volatile("ldmatrix.sync.aligned.m8n8.x4.shared.b16 {%0,%1,%2,%3}, [%4];"
                 : "=r"(r[0]), "=r"(r[1]), "=r"(r[2]), "=r"(r[3]) : "r"(a));
}

// ---------------- prep kernels ----------------
__global__ void f2h_kernel(const float* __restrict__ in,
                           __half* __restrict__ out, int n4) {
    int i = blockIdx.x * blockDim.x + threadIdx.x;
    if (i < n4) {
        float4 v = ((const float4*)in)[i];
        ((__half2*)out)[2 * i]     = __floats2half2_rn(v.x, v.y);
        ((__half2*)out)[2 * i + 1] = __floats2half2_rn(v.z, v.w);
    }
}
__global__ void transpose_h_kernel(const float* __restrict__ W,
                                   __half* __restrict__ Wt, int K, int N) {
    __shared__ float t[32][33];
    int k0 = blockIdx.y * 32, n0 = blockIdx.x * 32;
    int x = threadIdx.x, y = threadIdx.y;          // block (32,8)
    #pragma unroll
    for (int i = 0; i < 32; i += 8)
        t[y + i][x] = W[(size_t)(k0 + y + i) * N + n0 + x];
    __syncthreads();
    #pragma unroll
    for (int i = 0; i < 32; i += 8)
        Wt[(size_t)(n0 + y + i) * K + k0 + x] = __float2half_rn(t[x][y + i]);
}

// ---------------- generalized fp16 GEMM + bias (256x128 tile, ldmatrix) ---------
// C[M, :] = A[M,K] @ Bt[N,K]^T + bias[N]; strides lda/ldb/ldc; z-batch offsets.
#define SAH  40
#define ABYT (256 * SAH * 2)
#define BBYT (128 * SAH * 2)
#define STG  (ABYT + BBYT)
#define GEMM_SMEM (3 * STG)               // 92160 B

template <typename OutT>
__global__ __launch_bounds__(256, 1) void hgemm_bias(
    const __half* __restrict__ A, int lda, long zA,
    const __half* __restrict__ Bt, int ldb, long zB,
    const float* __restrict__ bias,
    OutT* __restrict__ C, int ldc, long zC,
    int Kdim)
{
    extern __shared__ __half smem[];
    A  += (size_t)blockIdx.z * zA;
    Bt += (size_t)blockIdx.z * zB;
    C  += (size_t)blockIdx.z * zC;

    const int tid  = threadIdx.x;
    const int warp = tid >> 5;
    const int lane = tid & 31;
    const int gid  = lane >> 2;
    const int tig  = lane & 3;
    const int wm   = (warp >> 1) * 64;
    const int wn   = (warp & 1)  * 64;
    const int bm   = blockIdx.y * 256;
    const int bn   = blockIdx.x * 128;

    const int crow = tid >> 2;
    const int cg   = (tid & 3) << 3;
    const __half* Agp = A  + (size_t)(bm + crow) * lda + cg;
    const __half* Bgp = Bt + (size_t)(bn + crow) * ldb + cg;
    const size_t a64 = (size_t)64 * lda;
    const size_t b64 = (size_t)64 * ldb;

    const int ktiles = Kdim >> 5;

    auto load_stage = [&](int s, int t) {
        __half* as = smem + s * (STG / 2);
        __half* bs = as + ABYT / 2;
        const int k0 = t << 5;
        #pragma unroll
        for (int i = 0; i < 4; i++)
            cp16(&as[(crow + i * 64) * SAH + cg], Agp + i * a64 + k0);
        #pragma unroll
        for (int i = 0; i < 2; i++)
            cp16(&bs[(crow + i * 64) * SAH + cg], Bgp + i * b64 + k0);
    };

    float acc[4][8][4];
    #pragma unroll
    for (int mt = 0; mt < 4; mt++)
        #pragma unroll
        for (int nt = 0; nt < 8; nt++)
            #pragma unroll
            for (int c = 0; c < 4; c++) acc[mt][nt][c] = 0.f;

    load_stage(0, 0); CP_COMMIT();
    if (ktiles > 1) load_stage(1, 1);
    CP_COMMIT();

    const int a_off = (wm + (lane & 15)) * SAH + ((lane >> 4) << 3);
    const int b_off = (wn + ((lane >> 4) << 3) + (lane & 7)) * SAH
                    + (((lane >> 3) & 1) << 3);

    for (int t = 0; t < ktiles; t++) {
        if (t + 2 < ktiles) load_stage((t + 2) % 3, t + 2);
        CP_COMMIT();
        CP_WAIT2();
        __syncthreads();

        const __half* as = smem + (t % 3) * (STG / 2);
        const __half* bs = as + ABYT / 2;
        #pragma unroll
        for (int ks = 0; ks < 2; ks++) {
            const int kh = ks << 4;
            unsigned afr[4][4], bfr[4][4];
            #pragma unroll
            for (int mt = 0; mt < 4; mt++)
                ldm_x4(afr[mt], as + a_off + mt * 16 * SAH + kh);
            #pragma unroll
            for (int np = 0; np < 4; np++)
                ldm_x4(bfr[np], bs + b_off + np * 16 * SAH + kh);
            #pragma unroll
            for (int mt = 0; mt < 4; mt++)
                #pragma unroll
                for (int nt = 0; nt < 8; nt++) {
                    const unsigned* bp = bfr[nt >> 1];
                    const int e = (nt & 1) << 1;
                    mma_f16(acc[mt][nt],
                            afr[mt][0], afr[mt][1], afr[mt][2], afr[mt][3],
                            bp[e], bp[e + 1]);
                }
        }
        __syncthreads();
    }

    #pragma unroll
    for (int mt = 0; mt < 4; mt++) {
        const int row0 = bm + wm + mt * 16 + gid;
        #pragma unroll
        for (int nt = 0; nt < 8; nt++) {
            const int col = bn + wn + nt * 8 + 2 * tig;
            const float b0 = bias[col], b1 = bias[col + 1];
            if constexpr (sizeof(OutT) == 4) {
                float2 o0, o1;
                o0.x = acc[mt][nt][0] + b0; o0.y = acc[mt][nt][1] + b1;
                o1.x = acc[mt][nt][2] + b0; o1.y = acc[mt][nt][3] + b1;
                *(float2*)&C[(size_t)row0 * ldc + col]       = o0;
                *(float2*)&C[(size_t)(row0 + 8) * ldc + col] = o1;
            } else {
                *(__half2*)&C[(size_t)row0 * ldc + col] =
                    __floats2half2_rn(acc[mt][nt][0] + b0, acc[mt][nt][1] + b1);
                *(__half2*)&C[(size_t)(row0 + 8) * ldc + col] =
                    __floats2half2_rn(acc[mt][nt][2] + b0, acc[mt][nt][3] + b1);
            }
        }
    }
}

// ---------------- svw GEMM: att[:, h*64+c] += s_h @ Wv_h + asum*bv_h ------------
// 256x64 tile, 8 warps (warp tile 32x64), 3-stage cp.async; epilogue adds
// existing att (out_self) and per-row asum * bv bias.
#define SVW_ABYT (256 * SAH * 2)          // 20480
#define SVW_BBYT (64 * SAH * 2)           // 5120
#define SVW_STG  (SVW_ABYT + SVW_BBYT)    // 25600
#define SVW_SMEM (3 * SVW_STG)            // 76800

__global__ __launch_bounds__(256, 1) void hgemm_svw(
    const __half* __restrict__ S,      // [12][8192][768]
    const __half* __restrict__ Wvt,    // g_wkvt (Wkv^T [1536][768])
    const float* __restrict__ bkv,     // bv_h = bkv + 768 + h*64
    const float* __restrict__ asum,    // [12][8192]
    __half* __restrict__ att)          // [8192][768] (contains out_self)
{
    extern __shared__ __half smem[];
    const int h = blockIdx.z;
    const __half* A  = S + (size_t)h * (B_ * N_) * D_;
    const __half* Bt = Wvt + (size_t)(D_ + h * DH) * D_;
    const float* bv  = bkv + D_ + h * DH;
    const float* ash = asum + (size_t)h * (B_ * N_);

    const int tid  = threadIdx.x;
    const int warp = tid >> 5;
    const int lane = tid & 31;
    const int gid  = lane >> 2;
    const int tig  = lane & 3;
    const int wm   = warp * 32;
    const int bm   = blockIdx.y * 256;

    const int crow = tid >> 2;
    const int cg   = (tid & 3) << 3;
    const __half* Agp = A  + (size_t)(bm + crow) * D_ + cg;
    const __half* Bgp = Bt + (size_t)crow * D_ + cg;     // only 64 B rows
    const size_t a64 = (size_t)64 * D_;

    const int ktiles = D_ >> 5;   // 24

    auto load_stage = [&](int s, int t) {
        __half* as = smem + s * (SVW_STG / 2);
        __half* bs = as + SVW_ABYT / 2;
        const int k0 = t << 5;
        #pragma unroll
        for (int i = 0; i < 4; i++)
            cp16(&as[(crow + i * 64) * SAH + cg], Agp + i * a64 + k0);
        cp16(&bs[crow * SAH + cg], Bgp + k0);
    };

    float acc[2][8][4];
    #pragma unroll
    for (int mt = 0; mt < 2; mt++)
        #pragma unroll
        for (int nt = 0; nt < 8; nt++)
            #pragma unroll
            for (int c = 0; c < 4; c++) acc[mt][nt][c] = 0.f;

    load_stage(0, 0); CP_COMMIT();
    load_stage(1, 1); CP_COMMIT();

    const int a_off = (wm + (lane & 15)) * SAH + ((lane >> 4) << 3);
    const int b_off = (((lane >> 4) << 3) + (lane & 7)) * SAH
                    + (((lane >> 3) & 1) << 3);

    for (int t = 0; t < ktiles; t++) {
        if (t + 2 < ktiles) load_stage((t + 2) % 3, t + 2);
        CP_COMMIT();
        CP_WAIT2();
        __syncthreads();

        const __half* as = smem + (t % 3) * (SVW_STG / 2);
        const __half* bs = as + SVW_ABYT / 2;
        #pragma unroll
        for (int ks = 0; ks < 2; ks++) {
            const int kh = ks << 4;
            unsigned afr[2][4], bfr[4][4];
            #pragma unroll
            for (int mt = 0; mt < 2; mt++)
                ldm_x4(afr[mt], as + a_off + mt * 16 * SAH + kh);
            #pragma unroll
            for (int np = 0; np < 4; np++)
                ldm_x4(bfr[np], bs + b_off + np * 16 * SAH + kh);
            #pragma unroll
            for (int mt = 0; mt < 2; mt++)
                #pragma unroll
                for (int nt = 0; nt < 8; nt++) {
                    const unsigned* bp = bfr[nt >> 1];
                    const int e = (nt & 1) << 1;
                    mma_f16(acc[mt][nt],
                            afr[mt][0], afr[mt][1], afr[mt][2], afr[mt][3],
                            bp[e], bp[e + 1]);
                }
        }
        __syncthreads();
    }

    #pragma unroll
    for (int mt = 0; mt < 2; mt++) {
        const int row0 = bm + wm + mt * 16 + gid;
        const float as0 = ash[row0], as1 = ash[row0 + 8];
        #pragma unroll
        for (int nt = 0; nt < 8; nt++) {
            const int col = nt * 8 + 2 * tig;
            const float b0 = bv[col], b1 = bv[col + 1];
            __half2* c0 = (__half2*)&att[(size_t)row0 * D_ + h * DH + col];
            __half2* c1 = (__half2*)&att[(size_t)(row0 + 8) * D_ + h * DH + col];
            float2 p0 = __half22float2(*c0);
            float2 p1 = __half22float2(*c1);
            *c0 = __floats2half2_rn(acc[mt][nt][0] + as0 * b0 + p0.x,
                                    acc[mt][nt][1] + as0 * b1 + p0.y);
            *c1 = __floats2half2_rn(acc[mt][nt][2] + as1 * b0 + p1.x,
                                    acc[mt][nt][3] + as1 * b1 + p1.y);
        }
    }
}

// ---------------- sim logits: ls[b,h,n,m] = sim[b,n,m,:] . t[b,n,h,:] ----------
__global__ __launch_bounds__(256) void logits_sim_kernel(
    const __half* __restrict__ simh,   // [8192][8][768]
    const __half* __restrict__ t,      // [8192][12][768]
    float* __restrict__ ls)            // [b][h][n][m] fp32
{
    __shared__ __half ssim[M_ * D_];
    __shared__ __half st[H_ * D_];
    const int bn = blockIdx.x;
    const int tid = threadIdx.x;
    const float4* sg = (const float4*)(simh + (size_t)bn * M_ * D_);
    float4* sd = (float4*)ssim;
    for (int i = tid; i < M_ * D_ / 8; i += 256) sd[i] = sg[i];
    const float4* tg = (const float4*)(t + (size_t)bn * H_ * D_);
    float4* td = (float4*)st;
    for (int i = tid; i < H_ * D_ / 8; i += 256) td[i] = tg[i];
    __syncthreads();

    const int warp = tid >> 5, lane = tid & 31;
    const int b = bn >> 9, n = bn & 511;
    const __half2* s2 = (const __half2*)ssim;
    const __half2* t2 = (const __half2*)st;
    for (int d = warp; d < H_ * M_; d += 8) {
        const int h = d >> 3, m = d & 7;
        float a = 0.f;
        #pragma unroll
        for (int j = 0; j < 12; j++) {
            float2 x = __half22float2(s2[m * 384 + lane + 32 * j]);
            float2 y = __half22float2(t2[h * 384 + lane + 32 * j]);
            a += x.x * y.x + x.y * y.y;
        }
        #pragma unroll
        for (int o = 16; o; o >>= 1) a += __shfl_xor_sync(0xffffffffu, a, o);
        if (lane == 0)
            ls[(((size_t)b * H_ + h) * N_ + n) * M_ + m] = a;
    }
}

// ---------------- s-pass: s[h][bn][:] = sum_m w[h][bn][m] * sim[bn][m][:] ------
__global__ __launch_bounds__(256) void spass_kernel(
    const __half* __restrict__ simh,   // [8192][8][768]
    const float* __restrict__ w,       // [12][8192][8]
    __half* __restrict__ s)            // [12][8192][768]
{
    __shared__ __half ssim[M_ * D_];
    __shared__ float sw[H_ * M_];
    const int bn = blockIdx.x;
    const int tid = threadIdx.x;
    const float4* sg = (const float4*)(simh + (size_t)bn * M_ * D_);
    float4* sd = (float4*)ssim;
    for (int i = tid; i < M_ * D_ / 8; i += 256) sd[i] = sg[i];
    if (tid < H_ * M_) {
        int h = tid >> 3, m = tid & 7;
        sw[tid] = w[((size_t)h * (B_ * N_) + bn) * M_ + m];
    }
    __syncthreads();

    const __half2* s2 = (const __half2*)ssim;
    for (int idx = tid; idx < H_ * 384; idx += 256) {
        const int h = idx / 384, c2 = idx % 384;
        float ax = 0.f, ay = 0.f;
        #pragma unroll
        for (int m = 0; m < M_; m++) {
            float2 v = __half22float2(s2[m * 384 + c2]);
            float wm_ = sw[h * M_ + m];
            ax += wm_ * v.x; ay += wm_ * v.y;
        }
        ((__half2*)s)[((size_t)h * (B_ * N_) + bn) * 384 + c2] =
            __floats2half2_rn(ax, ay);
    }
}

// ---------------- fused self-attention + sim-logit softmax ----------------
__global__ __launch_bounds__(256) void attn_kernel(
    const __half* __restrict__ qh,     // (B,N,D) half
    const float*  __restrict__ kv,     // (B,N,2D) fp32
    const float*  __restrict__ bkv,    // (2D,) fp32 (bk = first 768)
    const float*  __restrict__ ls,     // raw sim logits [b][h][n][m]
    __half* __restrict__ outa,         // (B,N,D) half : out_self normalized
    float* __restrict__ wg,            // [12][8192][8] normalized sim weights
    float* __restrict__ asum)          // [12][8192]
{
    extern __shared__ float sm[];
    float* qs = sm;               // 64*65
    float* ks = qs + 64 * 65;
    float* ps = ks + 64 * 65;
    float* vs = ps + 64 * 65;     // 64*64

    const int tid = threadIdx.x;
    const int n0 = blockIdx.x * 64;
    const int h  = blockIdx.y;
    const int b  = blockIdx.z;
    const float scale = kSCALE;

    // load Q tile (half -> fp32, pre-scaled)
    for (int i = tid; i < 512; i += 256) {
        int row = i >> 3;
        int g   = (i & 7) << 3;
        float4 raw = *(const float4*)&qh[(size_t)(b * N_ + n0 + row) * D_ + h * DH + g];
        const __half2* hp = (const __half2*)&raw;
        float* dst = &qs[row * 65 + g];
        #pragma unroll
        for (int j = 0; j < 4; j++) {
            float2 f = __half22float2(hp[j]);
            dst[2 * j]     = f.x * scale;
            dst[2 * j + 1] = f.y * scale;
        }
    }

    const int qi = tid >> 2;
    const int r  = tid & 3;
    const int tq = tid >> 4;
    const int tk = tid & 15;

    float m_i = -1e30f, l_i = 0.f;
    float acc[16];
    #pragma unroll
    for (int c = 0; c < 16; c++) acc[c] = 0.f;

    for (int kt = 0; kt < 8; kt++) {
        __syncthreads();
        for (int i = tid; i < 1024; i += 256) {
            int row = i >> 4;
            int c4  = (i & 15) << 2;
            size_t gbase = (size_t)(b * N_ + kt * 64 + row) * (2 * D_) + h * DH + c4;
            float4 kk = *(const float4*)&kv[gbase];
            float* kd = &ks[row * 65 + c4];
            kd[0] = kk.x; kd[1] = kk.y; kd[2] = kk.z; kd[3] = kk.w;
            *(float4*)&vs[row * 64 + c4] = *(const float4*)&kv[gbase + D_];
        }
        __syncthreads();

        float sc[4][4];
        #pragma unroll
        for (int i = 0; i < 4; i++)
            #pragma unroll
            for (int j = 0; j < 4; j++) sc[i][j] = 0.f;
        #pragma unroll 4
        for (int d = 0; d < 64; d++) {
            float qd[4], kd[4];
            #pragma unroll
            for (int i = 0; i < 4; i++) qd[i] = qs[(tq * 4 + i) * 65 + d];
            #pragma unroll
            for (int j = 0; j < 4; j++) kd[j] = ks[(tk * 4 + j) * 65 + d];
            #pragma unroll
            for (int i = 0; i < 4; i++)
                #pragma unroll
                for (int j = 0; j < 4; j++)
                    sc[i][j] += qd[i] * kd[j];
        }
        #pragma unroll
        for (int i = 0; i < 4; i++)
            #pragma unroll
            for (int j = 0; j < 4; j++)
                ps[(tq * 4 + i) * 65 + tk * 4 + j] = sc[i][j];
        __syncthreads();

        float pv[16];
        float tmax = -1e30f;
        #pragma unroll
        for (int j = 0; j < 16; j++) {
            pv[j] = ps[qi * 65 + 4 * j + r];
            tmax = fmaxf(tmax, pv[j]);
        }
        tmax = fmaxf(tmax, __shfl_xor_sync(0xffffffffu, tmax, 1));
        tmax = fmaxf(tmax, __shfl_xor_sync(0xffffffffu, tmax, 2));
        float nm   = fmaxf(m_i, tmax);
        float corr = __expf(m_i - nm);
        float psum = 0.f;
        #pragma unroll
        for (int j = 0; j < 16; j++) { pv[j] = __expf(pv[j] - nm); psum += pv[j]; }
        psum += __shfl_xor_sync(0xffffffffu, psum, 1);
        psum += __shfl_xor_sync(0xffffffffu, psum, 2);
        l_i = l_i * corr + psum;
        m_i = nm;
        #pragma unroll
        for (int c = 0; c < 16; c++) acc[c] *= corr;
        #pragma unroll
        for (int j = 0; j < 16; j++) ps[qi * 65 + 4 * j + r] = pv[j];
        __syncwarp();

        for (int kj = 0; kj < 64; kj++) {
            float p = ps[qi * 65 + kj];
            const float* vp = &vs[kj * 64 + r * 16];
            #pragma unroll
            for (int c4 = 0; c4 < 4; c4++) {
                float4 v = *(const float4*)&vp[c4 * 4];
                acc[c4 * 4 + 0] += p * v.x;
                acc[c4 * 4 + 1] += p * v.y;
                acc[c4 * 4 + 2] += p * v.z;
                acc[c4 * 4 + 3] += p * v.w;
            }
        }
    }

    // ---- sim logits: read precomputed raw logits, add SCALE*(q.bk_h) ----
    float p0, p1, inv;
    {
        // qbk = qs_row . bk_h (qs pre-scaled => equals SCALE*(q.bk))
        float qbk = 0.f;
        const float* bk = bkv + h * DH;
        #pragma unroll
        for (int d4 = 0; d4 < 4; d4++) {
            float4 bv4 = *(const float4*)&bk[r * 16 + d4 * 4];
            const float* qp = &qs[qi * 65 + r * 16 + d4 * 4];
            qbk += qp[0] * bv4.x + qp[1] * bv4.y + qp[2] * bv4.z + qp[3] * bv4.w;
        }
        qbk += __shfl_xor_sync(0xffffffffu, qbk, 1);
        qbk += __shfl_xor_sync(0xffffffffu, qbk, 2);

        float2 raw = *(const float2*)&ls[(((size_t)b * H_ + h) * N_ + n0 + qi) * M_ + 2 * r];
        float lg0 = scale * raw.x + qbk;
        float lg1 = scale * raw.y + qbk;

        float tmax = fmaxf(lg0, lg1);
        tmax = fmaxf(tmax, __shfl_xor_sync(0xffffffffu, tmax, 1));
        tmax = fmaxf(tmax, __shfl_xor_sync(0xffffffffu, tmax, 2));
        float nm   = fmaxf(m_i, tmax);
        float corr = __expf(m_i - nm);
        p0 = __expf(lg0 - nm);
        p1 = __expf(lg1 - nm);
        float psum = p0 + p1;
        psum += __shfl_xor_sync(0xffffffffu, psum, 1);
        psum += __shfl_xor_sync(0xffffffffu, psum, 2);
        l_i = l_i * corr + psum;
        #pragma unroll
        for (int c = 0; c < 16; c++) acc[c] *= corr;

        inv = 1.f / l_i;
        size_t widx = ((size_t)h * (B_ * N_) + b * N_ + n0 + qi);
        float2 wout; wout.x = p0 * inv; wout.y = p1 * inv;
        *(float2*)&wg[widx * M_ + 2 * r] = wout;
        if (r == 0) asum[widx] = psum * inv;
    }

    // write normalized out_self as half
    __half2* op = (__half2*)&outa[(size_t)(b * N_ + n0 + qi) * D_ + h * DH + r * 16];
    #pragma unroll
    for (int c4 = 0; c4 < 4; c4++) {
        op[c4 * 2 + 0] = __floats2half2_rn(acc[c4 * 4 + 0] * inv, acc[c4 * 4 + 1] * inv);
        op[c4 * 2 + 1] = __floats2half2_rn(acc[c4 * 4 + 2] * inv, acc[c4 * 4 + 3] * inv);
    }
}

// ---------------- launch ----------------
extern "C" void kernel_launch(void* const* d_in, const int* in_sizes, int n_in,
                              void* d_out, int out_size)
{
    const float* x   = (const float*)d_in[0];
    const float* sim = (const float*)d_in[1];
    const float* Wq  = (const float*)d_in[2];
    const float* bq  = (const float*)d_in[3];
    const float* Wkv = (const float*)d_in[4];
    const float* bkv = (const float*)d_in[5];
    const float* Wp  = (const float*)d_in[6];
    const float* bp  = (const float*)d_in[7];
    float* out = (float*)d_out;

    __half *qh, *att, *xh, *simh, *tt, *ss, *wqt, *wkvt, *wkvh, *wpt;
    float  *kvb, *ls, *wg, *asum, *zer;
    cudaGetSymbolAddress((void**)&qh,   g_qh);
    cudaGetSymbolAddress((void**)&kvb,  g_kv);
    cudaGetSymbolAddress((void**)&att,  g_att);
    cudaGetSymbolAddress((void**)&xh,   g_xh);
    cudaGetSymbolAddress((void**)&simh, g_simh);
    cudaGetSymbolAddress((void**)&tt,   g_t);
    cudaGetSymbolAddress((void**)&ss,   g_s);
    cudaGetSymbolAddress((void**)&ls,   g_ls);
    cudaGetSymbolAddress((void**)&wg,   g_w);
    cudaGetSymbolAddress((void**)&asum, g_asum);
    cudaGetSymbolAddress((void**)&wqt,  g_wqt);
    cudaGetSymbolAddress((void**)&wkvt, g_wkvt);
    cudaGetSymbolAddress((void**)&wkvh, g_wkvh);
    cudaGetSymbolAddress((void**)&wpt,  g_wpt);
    cudaGetSymbolAddress((void**)&zer,  g_zeros);

    const int ATTN_SMEM = (3 * 64 * 65 + 64 * 64) * sizeof(float); // 66304
    cudaFuncSetAttribute(attn_kernel,
                         cudaFuncAttributeMaxDynamicSharedMemorySize, ATTN_SMEM);
    cudaFuncSetAttribute(hgemm_bias<float>,
                         cudaFuncAttributeMaxDynamicSharedMemorySize, GEMM_SMEM);
    cudaFuncSetAttribute(hgemm_bias<__half>,
                         cudaFuncAttributeMaxDynamicSharedMemorySize, GEMM_SMEM);
    cudaFuncSetAttribute(hgemm_svw,
                         cudaFuncAttributeMaxDynamicSharedMemorySize, SVW_SMEM);

    const int BN  = B_ * N_;          // 8192
    const int BNM = B_ * N_ * M_;     // 65536

    // prep
    f2h_kernel<<<(BN * D_ / 4 + 255) / 256, 256>>>(x, xh, BN * D_ / 4);
    f2h_kernel<<<(BNM * D_ / 4 + 255) / 256, 256>>>(sim, simh, BNM * D_ / 4);
    f2h_kernel<<<(D_ * 2 * D_ / 4 + 255) / 256, 256>>>(Wkv, wkvh, D_ * 2 * D_ / 4);
    transpose_h_kernel<<<dim3(D_ / 32, D_ / 32), dim3(32, 8)>>>(Wq,  wqt,  D_, D_);
    transpose_h_kernel<<<dim3(2 * D_ / 32, D_ / 32), dim3(32, 8)>>>(Wkv, wkvt, D_, 2 * D_);
    transpose_h_kernel<<<dim3(D_ / 32, D_ / 32), dim3(32, 8)>>>(Wp,  wpt,  D_, D_);

    // q (half out) and kv (fp32 out)
    hgemm_bias<__half><<<dim3(D_ / 128, BN / 256), 256, GEMM_SMEM>>>(
        xh, D_, 0, wqt, D_, 0, bq, qh, D_, 0, D_);
    hgemm_bias<float><<<dim3(2 * D_ / 128, BN / 256), 256, GEMM_SMEM>>>(
        xh, D_, 0, wkvt, D_, 0, bkv, kvb, 2 * D_, 0, D_);

    // t_h = q_h @ Wk_h^T : batched over heads (z)
    hgemm_bias<__half><<<dim3(D_ / 128, BN / 256, H_), 256, GEMM_SMEM>>>(
        qh, D_, DH, wkvh, 2 * D_, DH, zer, tt, H_ * D_, D_, DH);

    // raw sim logits
    logits_sim_kernel<<<BN, 256>>>(simh, tt, ls);

    // attention: self tiles + sim-logit softmax; emits out_self, weights, asum
    attn_kernel<<<dim3(N_ / 64, H_, B_), 256, ATTN_SMEM>>>(
        qh, kvb, bkv, ls, att, wg, asum);

    // s[h] = sum_m w*sim ; then att += s_h @ Wv_h + asum*bv_h
    spass_kernel<<<BN, 256>>>(simh, wg, ss);
    hgemm_svw<<<dim3(1, BN / 256, H_), 256, SVW_SMEM>>>(ss, wkvt, bkv, asum, att);

    // final projection
    hgemm_bias<float><<<dim3(D_ / 128, BN / 256), 256, GEMM_SMEM>>>(
        att, D_, 0, wpt, D_, 0, bp, out, D_, 0, D_);
}

// round 8
// speedup vs baseline: 8.1201x; 2.4095x over previous
#include <cuda_runtime.h>
#include <cuda_fp16.h>
#include <cstdint>
#include <cstdio>

#define B_  16
#define N_  512
#define M_  8
#define D_  768
#define H_  12
#define DH  64
__device__ __constant__ float kSCALE = 0.125f; // 64^{-0.5}

// ---------------- scratch (device globals; no cudaMalloc allowed) ----------------
__device__ __half g_qh   [B_ * N_ * D_];             // q (B,N,D) half
__device__ __half g_kvh  [B_ * N_ * 2 * D_];         // (B,N,2D) half
__device__ __half g_att  [B_ * N_ * D_];             // out_self + out_sim (half)
__device__ __half g_xh   [B_ * N_ * D_];             // x half
__device__ __half g_simh [B_ * N_ * M_ * D_];        // sim half (100 MB)
__device__ __half g_t    [B_ * N_ * H_ * D_];        // t[bn][h][768] half
__device__ __half g_s    [H_ * B_ * N_ * D_];        // s[h][bn][768] half
__device__ float  g_ls   [B_ * H_ * N_ * M_];        // raw sim logits
__device__ float  g_w    [H_ * B_ * N_ * M_];        // normalized sim weights
__device__ float  g_asum [H_ * B_ * N_];             // sum of sim weights
__device__ __half g_wqt  [D_ * D_];                  // Wq^T  [N][K]
__device__ __half g_wkvt [2 * D_ * D_];              // Wkv^T [2D][D]
__device__ __half g_wkvh [D_ * 2 * D_];              // Wkv row-major half
__device__ __half g_wpt  [D_ * D_];                  // Wp^T
__device__ float  g_zeros[D_];                       // zero bias

// ---------------- helpers ----------------
__device__ __forceinline__ void cp16(void* smem_dst, const void* gmem_src) {
    unsigned s = (unsigned)__cvta_generic_to_shared(smem_dst);
    asm volatile("cp.async.cg.shared.global [%0], [%1], 16;\n"
                 :: "r"(s), "l"(gmem_src));
}
#define CP_COMMIT() asm volatile("cp.async.commit_group;\n" ::: "memory")
#define CP_WAIT2()  asm volatile("cp.async.wait_group 2;\n" ::: "memory")

__device__ __forceinline__ void mma_f16(float d[4],
                                        unsigned a0, unsigned a1, unsigned a2, unsigned a3,
                                        unsigned b0, unsigned b1)
{
    asm volatile(
        "mma.sync.aligned.m16n8k16.row.col.f32.f16.f16.f32 "
        "{%0,%1,%2,%3}, {%4,%5,%6,%7}, {%8,%9}, {%0,%1,%2,%3};\n"
        : "+f"(d[0]), "+f"(d[1]), "+f"(d[2]), "+f"(d[3])
        : "r"(a0), "r"(a1), "r"(a2), "r"(a3), "r"(b0), "r"(b1));
}
__device__ __forceinline__ void ldm_x4(unsigned r[4], const __half* p) {
    unsigned a = (unsigned)__cvta_generic_to_shared(p);
    asm volatile("ldmatrix.sync.aligned.m8n8.x4.shared.b16 {%0,%1,%2,%3}, [%4];"
                 : "=r"(r[0]), "=r"(r[1]), "=r"(r[2]), "=r"(r[3]) : "r"(a));
}
__device__ __forceinline__ void ldm_x4t(unsigned r[4], const __half* p) {
    unsigned a = (unsigned)__cvta_generic_to_shared(p);
    asm volatile("ldmatrix.sync.aligned.m8n8.x4.trans.shared.b16 {%0,%1,%2,%3}, [%4];"
                 : "=r"(r[0]), "=r"(r[1]), "=r"(r[2]), "=r"(r[3]) : "r"(a));
}
__device__ __forceinline__ unsigned packh2(float x, float y) {
    __half2 t = __floats2half2_rn(x, y);
    return *(unsigned*)&t;
}

// ---------------- prep kernels ----------------
__global__ void f2h_kernel(const float* __restrict__ in,
                           __half* __restrict__ out, int n4) {
    int i = blockIdx.x * blockDim.x + threadIdx.x;
    if (i < n4) {
        float4 v = ((const float4*)in)[i];
        ((__half2*)out)[2 * i]     = __floats2half2_rn(v.x, v.y);
        ((__half2*)out)[2 * i + 1] = __floats2half2_rn(v.z, v.w);
    }
}
__global__ void transpose_h_kernel(const float* __restrict__ W,
                                   __half* __restrict__ Wt, int K, int N) {
    __shared__ float t[32][33];
    int k0 = blockIdx.y * 32, n0 = blockIdx.x * 32;
    int x = threadIdx.x, y = threadIdx.y;
    #pragma unroll
    for (int i = 0; i < 32; i += 8)
        t[y + i][x] = W[(size_t)(k0 + y + i) * N + n0 + x];
    __syncthreads();
    #pragma unroll
    for (int i = 0; i < 32; i += 8)
        Wt[(size_t)(n0 + y + i) * K + k0 + x] = __float2half_rn(t[x][y + i]);
}

// ---------------- generalized fp16 GEMM + bias (256x128 tile, ldmatrix) ---------
#define SAH  40
#define ABYT (256 * SAH * 2)
#define BBYT (128 * SAH * 2)
#define STG  (ABYT + BBYT)
#define GEMM_SMEM (3 * STG)

template <typename OutT>
__global__ __launch_bounds__(256, 1) void hgemm_bias(
    const __half* __restrict__ A, int lda, long zA,
    const __half* __restrict__ Bt, int ldb, long zB,
    const float* __restrict__ bias,
    OutT* __restrict__ C, int ldc, long zC,
    int Kdim)
{
    extern __shared__ __half smem[];
    A  += (size_t)blockIdx.z * zA;
    Bt += (size_t)blockIdx.z * zB;
    C  += (size_t)blockIdx.z * zC;

    const int tid  = threadIdx.x;
    const int warp = tid >> 5;
    const int lane = tid & 31;
    const int gid  = lane >> 2;
    const int tig  = lane & 3;
    const int wm   = (warp >> 1) * 64;
    const int wn   = (warp & 1)  * 64;
    const int bm   = blockIdx.y * 256;
    const int bn   = blockIdx.x * 128;

    const int crow = tid >> 2;
    const int cg   = (tid & 3) << 3;
    const __half* Agp = A  + (size_t)(bm + crow) * lda + cg;
    const __half* Bgp = Bt + (size_t)(bn + crow) * ldb + cg;
    const size_t a64 = (size_t)64 * lda;
    const size_t b64 = (size_t)64 * ldb;

    const int ktiles = Kdim >> 5;

    auto load_stage = [&](int s, int t) {
        __half* as = smem + s * (STG / 2);
        __half* bs = as + ABYT / 2;
        const int k0 = t << 5;
        #pragma unroll
        for (int i = 0; i < 4; i++)
            cp16(&as[(crow + i * 64) * SAH + cg], Agp + i * a64 + k0);
        #pragma unroll
        for (int i = 0; i < 2; i++)
            cp16(&bs[(crow + i * 64) * SAH + cg], Bgp + i * b64 + k0);
    };

    float acc[4][8][4];
    #pragma unroll
    for (int mt = 0; mt < 4; mt++)
        #pragma unroll
        for (int nt = 0; nt < 8; nt++)
            #pragma unroll
            for (int c = 0; c < 4; c++) acc[mt][nt][c] = 0.f;

    load_stage(0, 0); CP_COMMIT();
    if (ktiles > 1) load_stage(1, 1);
    CP_COMMIT();

    const int a_off = (wm + (lane & 15)) * SAH + ((lane >> 4) << 3);
    const int b_off = (wn + ((lane >> 4) << 3) + (lane & 7)) * SAH
                    + (((lane >> 3) & 1) << 3);

    for (int t = 0; t < ktiles; t++) {
        if (t + 2 < ktiles) load_stage((t + 2) % 3, t + 2);
        CP_COMMIT();
        CP_WAIT2();
        __syncthreads();

        const __half* as = smem + (t % 3) * (STG / 2);
        const __half* bs = as + ABYT / 2;
        #pragma unroll
        for (int ks = 0; ks < 2; ks++) {
            const int kh = ks << 4;
            unsigned afr[4][4], bfr[4][4];
            #pragma unroll
            for (int mt = 0; mt < 4; mt++)
                ldm_x4(afr[mt], as + a_off + mt * 16 * SAH + kh);
            #pragma unroll
            for (int np = 0; np < 4; np++)
                ldm_x4(bfr[np], bs + b_off + np * 16 * SAH + kh);
            #pragma unroll
            for (int mt = 0; mt < 4; mt++)
                #pragma unroll
                for (int nt = 0; nt < 8; nt++) {
                    const unsigned* bp = bfr[nt >> 1];
                    const int e = (nt & 1) << 1;
                    mma_f16(acc[mt][nt],
                            afr[mt][0], afr[mt][1], afr[mt][2], afr[mt][3],
                            bp[e], bp[e + 1]);
                }
        }
        __syncthreads();
    }

    #pragma unroll
    for (int mt = 0; mt < 4; mt++) {
        const int row0 = bm + wm + mt * 16 + gid;
        #pragma unroll
        for (int nt = 0; nt < 8; nt++) {
            const int col = bn + wn + nt * 8 + 2 * tig;
            const float b0 = bias[col], b1 = bias[col + 1];
            if constexpr (sizeof(OutT) == 4) {
                float2 o0, o1;
                o0.x = acc[mt][nt][0] + b0; o0.y = acc[mt][nt][1] + b1;
                o1.x = acc[mt][nt][2] + b0; o1.y = acc[mt][nt][3] + b1;
                *(float2*)&C[(size_t)row0 * ldc + col]       = o0;
                *(float2*)&C[(size_t)(row0 + 8) * ldc + col] = o1;
            } else {
                *(__half2*)&C[(size_t)row0 * ldc + col] =
                    __floats2half2_rn(acc[mt][nt][0] + b0, acc[mt][nt][1] + b1);
                *(__half2*)&C[(size_t)(row0 + 8) * ldc + col] =
                    __floats2half2_rn(acc[mt][nt][2] + b0, acc[mt][nt][3] + b1);
            }
        }
    }
}

// ---------------- svw GEMM (unchanged from round 7) ----------------
#define SVW_ABYT (256 * SAH * 2)
#define SVW_BBYT (64 * SAH * 2)
#define SVW_STG  (SVW_ABYT + SVW_BBYT)
#define SVW_SMEM (3 * SVW_STG)

__global__ __launch_bounds__(256, 1) void hgemm_svw(
    const __half* __restrict__ S,
    const __half* __restrict__ Wvt,
    const float* __restrict__ bkv,
    const float* __restrict__ asum,
    __half* __restrict__ att)
{
    extern __shared__ __half smem[];
    const int h = blockIdx.z;
    const __half* A  = S + (size_t)h * (B_ * N_) * D_;
    const __half* Bt = Wvt + (size_t)(D_ + h * DH) * D_;
    const float* bv  = bkv + D_ + h * DH;
    const float* ash = asum + (size_t)h * (B_ * N_);

    const int tid  = threadIdx.x;
    const int warp = tid >> 5;
    const int lane = tid & 31;
    const int gid  = lane >> 2;
    const int tig  = lane & 3;
    const int wm   = warp * 32;
    const int bm   = blockIdx.y * 256;

    const int crow = tid >> 2;
    const int cg   = (tid & 3) << 3;
    const __half* Agp = A  + (size_t)(bm + crow) * D_ + cg;
    const __half* Bgp = Bt + (size_t)crow * D_ + cg;
    const size_t a64 = (size_t)64 * D_;

    const int ktiles = D_ >> 5;

    auto load_stage = [&](int s, int t) {
        __half* as = smem + s * (SVW_STG / 2);
        __half* bs = as + SVW_ABYT / 2;
        const int k0 = t << 5;
        #pragma unroll
        for (int i = 0; i < 4; i++)
            cp16(&as[(crow + i * 64) * SAH + cg], Agp + i * a64 + k0);
        cp16(&bs[crow * SAH + cg], Bgp + k0);
    };

    float acc[2][8][4];
    #pragma unroll
    for (int mt = 0; mt < 2; mt++)
        #pragma unroll
        for (int nt = 0; nt < 8; nt++)
            #pragma unroll
            for (int c = 0; c < 4; c++) acc[mt][nt][c] = 0.f;

    load_stage(0, 0); CP_COMMIT();
    load_stage(1, 1); CP_COMMIT();

    const int a_off = (wm + (lane & 15)) * SAH + ((lane >> 4) << 3);
    const int b_off = (((lane >> 4) << 3) + (lane & 7)) * SAH
                    + (((lane >> 3) & 1) << 3);

    for (int t = 0; t < ktiles; t++) {
        if (t + 2 < ktiles) load_stage((t + 2) % 3, t + 2);
        CP_COMMIT();
        CP_WAIT2();
        __syncthreads();

        const __half* as = smem + (t % 3) * (SVW_STG / 2);
        const __half* bs = as + SVW_ABYT / 2;
        #pragma unroll
        for (int ks = 0; ks < 2; ks++) {
            const int kh = ks << 4;
            unsigned afr[2][4], bfr[4][4];
            #pragma unroll
            for (int mt = 0; mt < 2; mt++)
                ldm_x4(afr[mt], as + a_off + mt * 16 * SAH + kh);
            #pragma unroll
            for (int np = 0; np < 4; np++)
                ldm_x4(bfr[np], bs + b_off + np * 16 * SAH + kh);
            #pragma unroll
            for (int mt = 0; mt < 2; mt++)
                #pragma unroll
                for (int nt = 0; nt < 8; nt++) {
                    const unsigned* bp = bfr[nt >> 1];
                    const int e = (nt & 1) << 1;
                    mma_f16(acc[mt][nt],
                            afr[mt][0], afr[mt][1], afr[mt][2], afr[mt][3],
                            bp[e], bp[e + 1]);
                }
        }
        __syncthreads();
    }

    #pragma unroll
    for (int mt = 0; mt < 2; mt++) {
        const int row0 = bm + wm + mt * 16 + gid;
        const float as0 = ash[row0], as1 = ash[row0 + 8];
        #pragma unroll
        for (int nt = 0; nt < 8; nt++) {
            const int col = nt * 8 + 2 * tig;
            const float b0 = bv[col], b1 = bv[col + 1];
            __half2* c0 = (__half2*)&att[(size_t)row0 * D_ + h * DH + col];
            __half2* c1 = (__half2*)&att[(size_t)(row0 + 8) * D_ + h * DH + col];
            float2 p0 = __half22float2(*c0);
            float2 p1 = __half22float2(*c1);
            *c0 = __floats2half2_rn(acc[mt][nt][0] + as0 * b0 + p0.x,
                                    acc[mt][nt][1] + as0 * b1 + p0.y);
            *c1 = __floats2half2_rn(acc[mt][nt][2] + as1 * b0 + p1.x,
                                    acc[mt][nt][3] + as1 * b1 + p1.y);
        }
    }
}

// ---------------- sim logits / s-pass (unchanged from round 7) ----------------
__global__ __launch_bounds__(256) void logits_sim_kernel(
    const __half* __restrict__ simh,
    const __half* __restrict__ t,
    float* __restrict__ ls)
{
    __shared__ __half ssim[M_ * D_];
    __shared__ __half st[H_ * D_];
    const int bn = blockIdx.x;
    const int tid = threadIdx.x;
    const float4* sg = (const float4*)(simh + (size_t)bn * M_ * D_);
    float4* sd = (float4*)ssim;
    for (int i = tid; i < M_ * D_ / 8; i += 256) sd[i] = sg[i];
    const float4* tg = (const float4*)(t + (size_t)bn * H_ * D_);
    float4* td = (float4*)st;
    for (int i = tid; i < H_ * D_ / 8; i += 256) td[i] = tg[i];
    __syncthreads();

    const int warp = tid >> 5, lane = tid & 31;
    const int b = bn >> 9, n = bn & 511;
    const __half2* s2 = (const __half2*)ssim;
    const __half2* t2 = (const __half2*)st;
    for (int d = warp; d < H_ * M_; d += 8) {
        const int h = d >> 3, m = d & 7;
        float a = 0.f;
        #pragma unroll
        for (int j = 0; j < 12; j++) {
            float2 x = __half22float2(s2[m * 384 + lane + 32 * j]);
            float2 y = __half22float2(t2[h * 384 + lane + 32 * j]);
            a += x.x * y.x + x.y * y.y;
        }
        #pragma unroll
        for (int o = 16; o; o >>= 1) a += __shfl_xor_sync(0xffffffffu, a, o);
        if (lane == 0)
            ls[(((size_t)b * H_ + h) * N_ + n) * M_ + m] = a;
    }
}

__global__ __launch_bounds__(256) void spass_kernel(
    const __half* __restrict__ simh,
    const float* __restrict__ w,
    __half* __restrict__ s)
{
    __shared__ __half ssim[M_ * D_];
    __shared__ float sw[H_ * M_];
    const int bn = blockIdx.x;
    const int tid = threadIdx.x;
    const float4* sg = (const float4*)(simh + (size_t)bn * M_ * D_);
    float4* sd = (float4*)ssim;
    for (int i = tid; i < M_ * D_ / 8; i += 256) sd[i] = sg[i];
    if (tid < H_ * M_) {
        int h = tid >> 3, m = tid & 7;
        sw[tid] = w[((size_t)h * (B_ * N_) + bn) * M_ + m];
    }
    __syncthreads();

    const __half2* s2 = (const __half2*)ssim;
    for (int idx = tid; idx < H_ * 384; idx += 256) {
        const int h = idx / 384, c2 = idx % 384;
        float ax = 0.f, ay = 0.f;
        #pragma unroll
        for (int m = 0; m < M_; m++) {
            float2 v = __half22float2(s2[m * 384 + c2]);
            float wm_ = sw[h * M_ + m];
            ax += wm_ * v.x; ay += wm_ * v.y;
        }
        ((__half2*)s)[((size_t)h * (B_ * N_) + bn) * 384 + c2] =
            __floats2half2_rn(ax, ay);
    }
}

// ---------------- tensor-core flash attention ----------------
// 128 threads = 4 warps, 16 queries each. S in registers; V via ldmatrix.trans.
#define SQV 72
#define TSZ (64 * SQV)                     // halves per 64x64 tile buffer
#define ATTN_SMEM_MMA (7 * TSZ * 2)        // Q + 3*K + 3*V = 64512 B

__global__ __launch_bounds__(128) void attn_mma_kernel(
    const __half* __restrict__ qh,     // (B,N,D)
    const __half* __restrict__ kvh,    // (B,N,2D)
    const float*  __restrict__ bkv,
    const float*  __restrict__ ls,     // raw sim logits [b][h][n][m]
    __half* __restrict__ outa,         // (B,N,D)
    float* __restrict__ wg,            // [12][8192][8]
    float* __restrict__ asum)          // [12][8192]
{
    extern __shared__ __half smh[];
    __half* sQ = smh;
    __half* sK = sQ + TSZ;
    __half* sV = sK + 3 * TSZ;

    const int tid = threadIdx.x;
    const int warp = tid >> 5, lane = tid & 31;
    const int gid = lane >> 2, tig = lane & 3;
    const int n0 = blockIdx.x * 64, h = blockIdx.y, b = blockIdx.z;
    const int wq = warp * 16;
    const float scale = kSCALE;
    const int bn0 = b * N_ + n0;

    // Q load (group 0, together with tile 0)
    {
        const int row = tid >> 3, g = (tid & 7) << 3;
        #pragma unroll
        for (int i = 0; i < 4; i++)
            cp16(&sQ[(row + i * 16) * SQV + g],
                 qh + (size_t)(bn0 + row + i * 16) * D_ + h * DH + g);
    }
    auto load_tile = [&](int st, int kt) {
        const int row = tid >> 3, g = (tid & 7) << 3;
        #pragma unroll
        for (int i = 0; i < 4; i++) {
            size_t gofs = (size_t)(b * N_ + kt * 64 + row + i * 16) * (2 * D_)
                        + h * DH + g;
            cp16(&sK[st * TSZ + (row + i * 16) * SQV + g], kvh + gofs);
            cp16(&sV[st * TSZ + (row + i * 16) * SQV + g], kvh + gofs + D_);
        }
    };
    load_tile(0, 0); CP_COMMIT();
    load_tile(1, 1); CP_COMMIT();

    float m_[2] = {-1e30f, -1e30f}, l_[2] = {0.f, 0.f};
    float o[8][4];
    #pragma unroll
    for (int nt = 0; nt < 8; nt++)
        #pragma unroll
        for (int c = 0; c < 4; c++) o[nt][c] = 0.f;

    unsigned qa[4][4];
    const int a_off = (wq + (lane & 15)) * SQV + ((lane >> 4) << 3);
    const int kb_off = (((lane >> 4) << 3) + (lane & 7)) * SQV
                     + (((lane >> 3) & 1) << 3);
    const int vb_off = (((lane >> 3) & 1) * 8 + (lane & 7)) * SQV
                     + ((lane >> 4) << 3);
    bool qloaded = false;

    for (int kt = 0; kt < 8; kt++) {
        if (kt + 2 < 8) load_tile((kt + 2) % 3, kt + 2);
        CP_COMMIT();
        CP_WAIT2();
        __syncthreads();

        if (!qloaded) {
            #pragma unroll
            for (int ks = 0; ks < 4; ks++)
                ldm_x4(qa[ks], sQ + a_off + ks * 16);
            qloaded = true;
        }

        const __half* kb = sK + (kt % 3) * TSZ;
        const __half* vb = sV + (kt % 3) * TSZ;

        // S = Q @ K^T
        float sc[8][4];
        #pragma unroll
        for (int nt = 0; nt < 8; nt++)
            #pragma unroll
            for (int c = 0; c < 4; c++) sc[nt][c] = 0.f;
        #pragma unroll
        for (int ks = 0; ks < 4; ks++) {
            unsigned kf[4][4];
            #pragma unroll
            for (int ng = 0; ng < 4; ng++)
                ldm_x4(kf[ng], kb + kb_off + ng * 16 * SQV + ks * 16);
            #pragma unroll
            for (int nt = 0; nt < 8; nt++) {
                const unsigned* bp = kf[nt >> 1];
                const int e = (nt & 1) << 1;
                mma_f16(sc[nt], qa[ks][0], qa[ks][1], qa[ks][2], qa[ks][3],
                        bp[e], bp[e + 1]);
            }
        }
        #pragma unroll
        for (int nt = 0; nt < 8; nt++)
            #pragma unroll
            for (int c = 0; c < 4; c++) sc[nt][c] *= scale;

        // online softmax per row slot (0: row gid; 1: row gid+8)
        #pragma unroll
        for (int s = 0; s < 2; s++) {
            const int e = s << 1;
            float tmax = -1e30f;
            #pragma unroll
            for (int nt = 0; nt < 8; nt++)
                tmax = fmaxf(tmax, fmaxf(sc[nt][e], sc[nt][e + 1]));
            tmax = fmaxf(tmax, __shfl_xor_sync(0xffffffffu, tmax, 1));
            tmax = fmaxf(tmax, __shfl_xor_sync(0xffffffffu, tmax, 2));
            float nm = fmaxf(m_[s], tmax);
            float corr = __expf(m_[s] - nm);
            float sum = 0.f;
            #pragma unroll
            for (int nt = 0; nt < 8; nt++) {
                sc[nt][e]     = __expf(sc[nt][e] - nm);
                sc[nt][e + 1] = __expf(sc[nt][e + 1] - nm);
                sum += sc[nt][e] + sc[nt][e + 1];
            }
            sum += __shfl_xor_sync(0xffffffffu, sum, 1);
            sum += __shfl_xor_sync(0xffffffffu, sum, 2);
            l_[s] = l_[s] * corr + sum;
            m_[s] = nm;
            #pragma unroll
            for (int nt = 0; nt < 8; nt++) {
                o[nt][e]     *= corr;
                o[nt][e + 1] *= corr;
            }
        }

        // P -> half A-fragments
        unsigned pa[4][4];
        #pragma unroll
        for (int kc = 0; kc < 4; kc++) {
            pa[kc][0] = packh2(sc[2 * kc][0],     sc[2 * kc][1]);
            pa[kc][1] = packh2(sc[2 * kc][2],     sc[2 * kc][3]);
            pa[kc][2] = packh2(sc[2 * kc + 1][0], sc[2 * kc + 1][1]);
            pa[kc][3] = packh2(sc[2 * kc + 1][2], sc[2 * kc + 1][3]);
        }

        // O += P @ V
        #pragma unroll
        for (int kc = 0; kc < 4; kc++) {
            unsigned vf[4][4];
            #pragma unroll
            for (int ng = 0; ng < 4; ng++)
                ldm_x4t(vf[ng], vb + vb_off + kc * 16 * SQV + ng * 16);
            #pragma unroll
            for (int nt = 0; nt < 8; nt++) {
                const unsigned* bp = vf[nt >> 1];
                const int e = (nt & 1) << 1;
                mma_f16(o[nt], pa[kc][0], pa[kc][1], pa[kc][2], pa[kc][3],
                        bp[e], bp[e + 1]);
            }
        }
        __syncthreads();
    }

    // ---- sim logits + final normalize + writes ----
    #pragma unroll
    for (int s = 0; s < 2; s++) {
        const int rl = wq + gid + s * 8;         // local query row
        const int e = s << 1;

        // qbk = q_row . bk_h (raw)
        float qbk = 0.f;
        {
            const __half2* qp = (const __half2*)&sQ[rl * SQV + tig * 16];
            const float* bk = bkv + h * DH + tig * 16;
            #pragma unroll
            for (int j = 0; j < 8; j++) {
                float2 f = __half22float2(qp[j]);
                qbk += f.x * bk[2 * j] + f.y * bk[2 * j + 1];
            }
            qbk += __shfl_xor_sync(0xffffffffu, qbk, 1);
            qbk += __shfl_xor_sync(0xffffffffu, qbk, 2);
        }

        float2 raw = *(const float2*)&ls[(((size_t)b * H_ + h) * N_ + n0 + rl) * M_ + 2 * tig];
        float lg0 = scale * (raw.x + qbk);
        float lg1 = scale * (raw.y + qbk);

        float tmax = fmaxf(lg0, lg1);
        tmax = fmaxf(tmax, __shfl_xor_sync(0xffffffffu, tmax, 1));
        tmax = fmaxf(tmax, __shfl_xor_sync(0xffffffffu, tmax, 2));
        float nm = fmaxf(m_[s], tmax);
        float corr = __expf(m_[s] - nm);
        float p0 = __expf(lg0 - nm);
        float p1 = __expf(lg1 - nm);
        float ps = p0 + p1;
        ps += __shfl_xor_sync(0xffffffffu, ps, 1);
        ps += __shfl_xor_sync(0xffffffffu, ps, 2);
        float lnew = l_[s] * corr + ps;
        float inv = 1.f / lnew;

        size_t widx = (size_t)h * (B_ * N_) + bn0 + rl;
        float2 wout; wout.x = p0 * inv; wout.y = p1 * inv;
        *(float2*)&wg[widx * M_ + 2 * tig] = wout;
        if (tig == 0) asum[widx] = ps * inv;

        const float ci = corr * inv;
        __half2* op = (__half2*)&outa[(size_t)(bn0 + rl) * D_ + h * DH];
        #pragma unroll
        for (int nt = 0; nt < 8; nt++)
            op[nt * 4 + tig] = __floats2half2_rn(o[nt][e] * ci, o[nt][e + 1] * ci);
    }
}

// ---------------- launch ----------------
extern "C" void kernel_launch(void* const* d_in, const int* in_sizes, int n_in,
                              void* d_out, int out_size)
{
    const float* x   = (const float*)d_in[0];
    const float* sim = (const float*)d_in[1];
    const float* Wq  = (const float*)d_in[2];
    const float* bq  = (const float*)d_in[3];
    const float* Wkv = (const float*)d_in[4];
    const float* bkv = (const float*)d_in[5];
    const float* Wp  = (const float*)d_in[6];
    const float* bp  = (const float*)d_in[7];
    float* out = (float*)d_out;

    __half *qh, *kvh, *att, *xh, *simh, *tt, *ss, *wqt, *wkvt, *wkvh, *wpt;
    float  *ls, *wg, *asum, *zer;
    cudaGetSymbolAddress((void**)&qh,   g_qh);
    cudaGetSymbolAddress((void**)&kvh,  g_kvh);
    cudaGetSymbolAddress((void**)&att,  g_att);
    cudaGetSymbolAddress((void**)&xh,   g_xh);
    cudaGetSymbolAddress((void**)&simh, g_simh);
    cudaGetSymbolAddress((void**)&tt,   g_t);
    cudaGetSymbolAddress((void**)&ss,   g_s);
    cudaGetSymbolAddress((void**)&ls,   g_ls);
    cudaGetSymbolAddress((void**)&wg,   g_w);
    cudaGetSymbolAddress((void**)&asum, g_asum);
    cudaGetSymbolAddress((void**)&wqt,  g_wqt);
    cudaGetSymbolAddress((void**)&wkvt, g_wkvt);
    cudaGetSymbolAddress((void**)&wkvh, g_wkvh);
    cudaGetSymbolAddress((void**)&wpt,  g_wpt);
    cudaGetSymbolAddress((void**)&zer,  g_zeros);

    cudaFuncSetAttribute(attn_mma_kernel,
                         cudaFuncAttributeMaxDynamicSharedMemorySize, ATTN_SMEM_MMA);
    cudaFuncSetAttribute(hgemm_bias<float>,
                         cudaFuncAttributeMaxDynamicSharedMemorySize, GEMM_SMEM);
    cudaFuncSetAttribute(hgemm_bias<__half>,
                         cudaFuncAttributeMaxDynamicSharedMemorySize, GEMM_SMEM);
    cudaFuncSetAttribute(hgemm_svw,
                         cudaFuncAttributeMaxDynamicSharedMemorySize, SVW_SMEM);

    const int BN  = B_ * N_;
    const int BNM = B_ * N_ * M_;

    // prep
    f2h_kernel<<<(BN * D_ / 4 + 255) / 256, 256>>>(x, xh, BN * D_ / 4);
    f2h_kernel<<<(BNM * D_ / 4 + 255) / 256, 256>>>(sim, simh, BNM * D_ / 4);
    f2h_kernel<<<(D_ * 2 * D_ / 4 + 255) / 256, 256>>>(Wkv, wkvh, D_ * 2 * D_ / 4);
    transpose_h_kernel<<<dim3(D_ / 32, D_ / 32), dim3(32, 8)>>>(Wq,  wqt,  D_, D_);
    transpose_h_kernel<<<dim3(2 * D_ / 32, D_ / 32), dim3(32, 8)>>>(Wkv, wkvt, D_, 2 * D_);
    transpose_h_kernel<<<dim3(D_ / 32, D_ / 32), dim3(32, 8)>>>(Wp,  wpt,  D_, D_);

    // projections
    hgemm_bias<__half><<<dim3(D_ / 128, BN / 256), 256, GEMM_SMEM>>>(
        xh, D_, 0, wqt, D_, 0, bq, qh, D_, 0, D_);
    hgemm_bias<__half><<<dim3(2 * D_ / 128, BN / 256), 256, GEMM_SMEM>>>(
        xh, D_, 0, wkvt, D_, 0, bkv, kvh, 2 * D_, 0, D_);

    // t_h = q_h @ Wk_h^T (batched over heads)
    hgemm_bias<__half><<<dim3(D_ / 128, BN / 256, H_), 256, GEMM_SMEM>>>(
        qh, D_, DH, wkvh, 2 * D_, DH, zer, tt, H_ * D_, D_, DH);

    // raw sim logits
    logits_sim_kernel<<<BN, 256>>>(simh, tt, ls);

    // flash attention (tensor cores)
    attn_mma_kernel<<<dim3(N_ / 64, H_, B_), 128, ATTN_SMEM_MMA>>>(
        qh, kvh, bkv, ls, att, wg, asum);

    // s[h] = sum_m w*sim ; att += s_h @ Wv_h + asum*bv_h
    spass_kernel<<<BN, 256>>>(simh, wg, ss);
    hgemm_svw<<<dim3(1, BN / 256, H_), 256, SVW_SMEM>>>(ss, wkvt, bkv, asum, att);

    // final projection
    hgemm_bias<float><<<dim3(D_ / 128, BN / 256), 256, GEMM_SMEM>>>(
        att, D_, 0, wpt, D_, 0, bp, out, D_, 0, D_);
}

// round 9
// speedup vs baseline: 8.6100x; 1.0603x over previous
#include <cuda_runtime.h>
#include <cuda_fp16.h>
#include <cstdint>
#include <cstdio>

#define B_  16
#define N_  512
#define M_  8
#define D_  768
#define H_  12
#define DH  64
#define QKVW 2304
__device__ __constant__ float kSCALE = 0.125f; // 64^{-0.5}

// ---------------- scratch ----------------
__device__ __half g_qkv  [B_ * N_ * QKVW];           // [q | k | v] half
__device__ __half g_att  [B_ * N_ * D_];             // out_self + out_sim
__device__ __half g_xh   [B_ * N_ * D_];             // x half
__device__ __half g_t    [B_ * N_ * H_ * D_];        // t[bn][h][768]
__device__ __half g_s    [H_ * B_ * N_ * D_];        // s[h][bn][768]
__device__ float  g_ls   [B_ * H_ * N_ * M_];        // raw sim logits
__device__ float  g_w    [H_ * B_ * N_ * M_];        // normalized sim weights
__device__ float  g_asum [H_ * B_ * N_];
__device__ __half g_wqkvt[QKVW * D_];                // [Wq^T ; Wkv^T]
__device__ __half g_wkvh [D_ * 2 * D_];              // Wkv row-major half
__device__ __half g_wpt  [D_ * D_];
__device__ float  g_bqkv [QKVW];                     // [bq ; bkv]
__device__ float  g_zeros[D_];

// ---------------- helpers ----------------
__device__ __forceinline__ void cp16(void* smem_dst, const void* gmem_src) {
    unsigned s = (unsigned)__cvta_generic_to_shared(smem_dst);
    asm volatile("cp.async.cg.shared.global [%0], [%1], 16;\n"
                 :: "r"(s), "l"(gmem_src));
}
#define CP_COMMIT() asm volatile("cp.async.commit_group;\n" ::: "memory")
#define CP_WAIT2()  asm volatile("cp.async.wait_group 2;\n" ::: "memory")

__device__ __forceinline__ void mma_f16(float d[4],
                                        unsigned a0, unsigned a1, unsigned a2, unsigned a3,
                                        unsigned b0, unsigned b1)
{
    asm volatile(
        "mma.sync.aligned.m16n8k16.row.col.f32.f16.f16.f32 "
        "{%0,%1,%2,%3}, {%4,%5,%6,%7}, {%8,%9}, {%0,%1,%2,%3};\n"
        : "+f"(d[0]), "+f"(d[1]), "+f"(d[2]), "+f"(d[3])
        : "r"(a0), "r"(a1), "r"(a2), "r"(a3), "r"(b0), "r"(b1));
}
__device__ __forceinline__ void ldm_x4(unsigned r[4], const __half* p) {
    unsigned a = (unsigned)__cvta_generic_to_shared(p);
    asm volatile("ldmatrix.sync.aligned.m8n8.x4.shared.b16 {%0,%1,%2,%3}, [%4];"
                 : "=r"(r[0]), "=r"(r[1]), "=r"(r[2]), "=r"(r[3]) : "r"(a));
}
__device__ __forceinline__ void ldm_x4t(unsigned r[4], const __half* p) {
    unsigned a = (unsigned)__cvta_generic_to_shared(p);
    asm volatile("ldmatrix.sync.aligned.m8n8.x4.trans.shared.b16 {%0,%1,%2,%3}, [%4];"
                 : "=r"(r[0]), "=r"(r[1]), "=r"(r[2]), "=r"(r[3]) : "r"(a));
}
__device__ __forceinline__ unsigned packh2(float x, float y) {
    __half2 t = __floats2half2_rn(x, y);
    return *(unsigned*)&t;
}

// ---------------- prep kernels ----------------
__global__ void biascat_kernel(const float* __restrict__ bq,
                               const float* __restrict__ bkv,
                               float* __restrict__ bqkv) {
    int i = blockIdx.x * blockDim.x + threadIdx.x;
    if (i < D_) bqkv[i] = bq[i];
    else if (i < QKVW) bqkv[i] = bkv[i - D_];
}
__global__ void f2h_kernel(const float* __restrict__ in,
                           __half* __restrict__ out, int n4) {
    int i = blockIdx.x * blockDim.x + threadIdx.x;
    if (i < n4) {
        float4 v = ((const float4*)in)[i];
        ((__half2*)out)[2 * i]     = __floats2half2_rn(v.x, v.y);
        ((__half2*)out)[2 * i + 1] = __floats2half2_rn(v.z, v.w);
    }
}
__global__ void transpose_h_kernel(const float* __restrict__ W,
                                   __half* __restrict__ Wt, int K, int N) {
    __shared__ float t[32][33];
    int k0 = blockIdx.y * 32, n0 = blockIdx.x * 32;
    int x = threadIdx.x, y = threadIdx.y;
    #pragma unroll
    for (int i = 0; i < 32; i += 8)
        t[y + i][x] = W[(size_t)(k0 + y + i) * N + n0 + x];
    __syncthreads();
    #pragma unroll
    for (int i = 0; i < 32; i += 8)
        Wt[(size_t)(n0 + y + i) * K + k0 + x] = __float2half_rn(t[x][y + i]);
}

// ---------------- generalized fp16 GEMM + bias (256x128 tile, ldmatrix) ---------
#define SAH  40
#define ABYT (256 * SAH * 2)
#define BBYT (128 * SAH * 2)
#define STG  (ABYT + BBYT)
#define GEMM_SMEM (3 * STG)

template <typename OutT>
__global__ __launch_bounds__(256, 1) void hgemm_bias(
    const __half* __restrict__ A, int lda, long zA,
    const __half* __restrict__ Bt, int ldb, long zB,
    const float* __restrict__ bias,
    OutT* __restrict__ C, int ldc, long zC,
    int Kdim)
{
    extern __shared__ __half smem[];
    A  += (size_t)blockIdx.z * zA;
    Bt += (size_t)blockIdx.z * zB;
    C  += (size_t)blockIdx.z * zC;

    const int tid  = threadIdx.x;
    const int warp = tid >> 5;
    const int lane = tid & 31;
    const int gid  = lane >> 2;
    const int tig  = lane & 3;
    const int wm   = (warp >> 1) * 64;
    const int wn   = (warp & 1)  * 64;
    const int bm   = blockIdx.y * 256;
    const int bn   = blockIdx.x * 128;

    const int crow = tid >> 2;
    const int cg   = (tid & 3) << 3;
    const __half* Agp = A  + (size_t)(bm + crow) * lda + cg;
    const __half* Bgp = Bt + (size_t)(bn + crow) * ldb + cg;
    const size_t a64 = (size_t)64 * lda;
    const size_t b64 = (size_t)64 * ldb;

    const int ktiles = Kdim >> 5;

    auto load_stage = [&](int s, int t) {
        __half* as = smem + s * (STG / 2);
        __half* bs = as + ABYT / 2;
        const int k0 = t << 5;
        #pragma unroll
        for (int i = 0; i < 4; i++)
            cp16(&as[(crow + i * 64) * SAH + cg], Agp + i * a64 + k0);
        #pragma unroll
        for (int i = 0; i < 2; i++)
            cp16(&bs[(crow + i * 64) * SAH + cg], Bgp + i * b64 + k0);
    };

    float acc[4][8][4];
    #pragma unroll
    for (int mt = 0; mt < 4; mt++)
        #pragma unroll
        for (int nt = 0; nt < 8; nt++)
            #pragma unroll
            for (int c = 0; c < 4; c++) acc[mt][nt][c] = 0.f;

    load_stage(0, 0); CP_COMMIT();
    if (ktiles > 1) load_stage(1, 1);
    CP_COMMIT();

    const int a_off = (wm + (lane & 15)) * SAH + ((lane >> 4) << 3);
    const int b_off = (wn + ((lane >> 4) << 3) + (lane & 7)) * SAH
                    + (((lane >> 3) & 1) << 3);

    for (int t = 0; t < ktiles; t++) {
        if (t + 2 < ktiles) load_stage((t + 2) % 3, t + 2);
        CP_COMMIT();
        CP_WAIT2();
        __syncthreads();

        const __half* as = smem + (t % 3) * (STG / 2);
        const __half* bs = as + ABYT / 2;
        #pragma unroll
        for (int ks = 0; ks < 2; ks++) {
            const int kh = ks << 4;
            unsigned afr[4][4], bfr[4][4];
            #pragma unroll
            for (int mt = 0; mt < 4; mt++)
                ldm_x4(afr[mt], as + a_off + mt * 16 * SAH + kh);
            #pragma unroll
            for (int np = 0; np < 4; np++)
                ldm_x4(bfr[np], bs + b_off + np * 16 * SAH + kh);
            #pragma unroll
            for (int mt = 0; mt < 4; mt++)
                #pragma unroll
                for (int nt = 0; nt < 8; nt++) {
                    const unsigned* bp = bfr[nt >> 1];
                    const int e = (nt & 1) << 1;
                    mma_f16(acc[mt][nt],
                            afr[mt][0], afr[mt][1], afr[mt][2], afr[mt][3],
                            bp[e], bp[e + 1]);
                }
        }
        __syncthreads();
    }

    #pragma unroll
    for (int mt = 0; mt < 4; mt++) {
        const int row0 = bm + wm + mt * 16 + gid;
        #pragma unroll
        for (int nt = 0; nt < 8; nt++) {
            const int col = bn + wn + nt * 8 + 2 * tig;
            const float b0 = bias[col], b1 = bias[col + 1];
            if constexpr (sizeof(OutT) == 4) {
                float2 o0, o1;
                o0.x = acc[mt][nt][0] + b0; o0.y = acc[mt][nt][1] + b1;
                o1.x = acc[mt][nt][2] + b0; o1.y = acc[mt][nt][3] + b1;
                *(float2*)&C[(size_t)row0 * ldc + col]       = o0;
                *(float2*)&C[(size_t)(row0 + 8) * ldc + col] = o1;
            } else {
                *(__half2*)&C[(size_t)row0 * ldc + col] =
                    __floats2half2_rn(acc[mt][nt][0] + b0, acc[mt][nt][1] + b1);
                *(__half2*)&C[(size_t)(row0 + 8) * ldc + col] =
                    __floats2half2_rn(acc[mt][nt][2] + b0, acc[mt][nt][3] + b1);
            }
        }
    }
}

// ---------------- svw GEMM ----------------
#define SVW_ABYT (256 * SAH * 2)
#define SVW_BBYT (64 * SAH * 2)
#define SVW_STG  (SVW_ABYT + SVW_BBYT)
#define SVW_SMEM (3 * SVW_STG)

__global__ __launch_bounds__(256, 1) void hgemm_svw(
    const __half* __restrict__ S,
    const __half* __restrict__ Wkvt,
    const float* __restrict__ bkv,
    const float* __restrict__ asum,
    __half* __restrict__ att)
{
    extern __shared__ __half smem[];
    const int h = blockIdx.z;
    const __half* A  = S + (size_t)h * (B_ * N_) * D_;
    const __half* Bt = Wkvt + (size_t)(D_ + h * DH) * D_;
    const float* bv  = bkv + D_ + h * DH;
    const float* ash = asum + (size_t)h * (B_ * N_);

    const int tid  = threadIdx.x;
    const int warp = tid >> 5;
    const int lane = tid & 31;
    const int gid  = lane >> 2;
    const int tig  = lane & 3;
    const int wm   = warp * 32;
    const int bm   = blockIdx.y * 256;

    const int crow = tid >> 2;
    const int cg   = (tid & 3) << 3;
    const __half* Agp = A  + (size_t)(bm + crow) * D_ + cg;
    const __half* Bgp = Bt + (size_t)crow * D_ + cg;
    const size_t a64 = (size_t)64 * D_;

    const int ktiles = D_ >> 5;

    auto load_stage = [&](int s, int t) {
        __half* as = smem + s * (SVW_STG / 2);
        __half* bs = as + SVW_ABYT / 2;
        const int k0 = t << 5;
        #pragma unroll
        for (int i = 0; i < 4; i++)
            cp16(&as[(crow + i * 64) * SAH + cg], Agp + i * a64 + k0);
        cp16(&bs[crow * SAH + cg], Bgp + k0);
    };

    float acc[2][8][4];
    #pragma unroll
    for (int mt = 0; mt < 2; mt++)
        #pragma unroll
        for (int nt = 0; nt < 8; nt++)
            #pragma unroll
            for (int c = 0; c < 4; c++) acc[mt][nt][c] = 0.f;

    load_stage(0, 0); CP_COMMIT();
    load_stage(1, 1); CP_COMMIT();

    const int a_off = (wm + (lane & 15)) * SAH + ((lane >> 4) << 3);
    const int b_off = (((lane >> 4) << 3) + (lane & 7)) * SAH
                    + (((lane >> 3) & 1) << 3);

    for (int t = 0; t < ktiles; t++) {
        if (t + 2 < ktiles) load_stage((t + 2) % 3, t + 2);
        CP_COMMIT();
        CP_WAIT2();
        __syncthreads();

        const __half* as = smem + (t % 3) * (SVW_STG / 2);
        const __half* bs = as + SVW_ABYT / 2;
        #pragma unroll
        for (int ks = 0; ks < 2; ks++) {
            const int kh = ks << 4;
            unsigned afr[2][4], bfr[4][4];
            #pragma unroll
            for (int mt = 0; mt < 2; mt++)
                ldm_x4(afr[mt], as + a_off + mt * 16 * SAH + kh);
            #pragma unroll
            for (int np = 0; np < 4; np++)
                ldm_x4(bfr[np], bs + b_off + np * 16 * SAH + kh);
            #pragma unroll
            for (int mt = 0; mt < 2; mt++)
                #pragma unroll
                for (int nt = 0; nt < 8; nt++) {
                    const unsigned* bp = bfr[nt >> 1];
                    const int e = (nt & 1) << 1;
                    mma_f16(acc[mt][nt],
                            afr[mt][0], afr[mt][1], afr[mt][2], afr[mt][3],
                            bp[e], bp[e + 1]);
                }
        }
        __syncthreads();
    }

    #pragma unroll
    for (int mt = 0; mt < 2; mt++) {
        const int row0 = bm + wm + mt * 16 + gid;
        const float as0 = ash[row0], as1 = ash[row0 + 8];
        #pragma unroll
        for (int nt = 0; nt < 8; nt++) {
            const int col = nt * 8 + 2 * tig;
            const float b0 = bv[col], b1 = bv[col + 1];
            __half2* c0 = (__half2*)&att[(size_t)row0 * D_ + h * DH + col];
            __half2* c1 = (__half2*)&att[(size_t)(row0 + 8) * D_ + h * DH + col];
            float2 p0 = __half22float2(*c0);
            float2 p1 = __half22float2(*c1);
            *c0 = __floats2half2_rn(acc[mt][nt][0] + as0 * b0 + p0.x,
                                    acc[mt][nt][1] + as0 * b1 + p0.y);
            *c1 = __floats2half2_rn(acc[mt][nt][2] + as1 * b0 + p1.x,
                                    acc[mt][nt][3] + as1 * b1 + p1.y);
        }
    }
}

// ---------------- sim logits (fp32 sim input) ----------------
__global__ __launch_bounds__(256) void logits_sim_kernel(
    const float* __restrict__ sim,     // [8192][8][768] fp32
    const __half* __restrict__ t,      // [8192][12][768]
    float* __restrict__ ls)
{
    __shared__ float  ssim[M_ * D_];   // 24576 B
    __shared__ __half st[H_ * D_];     // 18432 B
    const int bn = blockIdx.x;
    const int tid = threadIdx.x;
    const float4* sg = (const float4*)(sim + (size_t)bn * M_ * D_);
    float4* sd = (float4*)ssim;
    for (int i = tid; i < M_ * D_ / 4; i += 256) sd[i] = sg[i];
    const float4* tg = (const float4*)(t + (size_t)bn * H_ * D_);
    float4* td = (float4*)st;
    for (int i = tid; i < H_ * D_ / 8; i += 256) td[i] = tg[i];
    __syncthreads();

    const int warp = tid >> 5, lane = tid & 31;
    const int b = bn >> 9, n = bn & 511;
    const float2* s2 = (const float2*)ssim;
    const __half2* t2 = (const __half2*)st;
    for (int d = warp; d < H_ * M_; d += 8) {
        const int h = d >> 3, m = d & 7;
        float a = 0.f;
        #pragma unroll
        for (int j = 0; j < 12; j++) {
            float2 x = s2[m * 384 + lane + 32 * j];
            float2 y = __half22float2(t2[h * 384 + lane + 32 * j]);
            a += x.x * y.x + x.y * y.y;
        }
        #pragma unroll
        for (int o = 16; o; o >>= 1) a += __shfl_xor_sync(0xffffffffu, a, o);
        if (lane == 0)
            ls[(((size_t)b * H_ + h) * N_ + n) * M_ + m] = a;
    }
}

// ---------------- s-pass (fp32 sim input) ----------------
__global__ __launch_bounds__(256) void spass_kernel(
    const float* __restrict__ sim,     // [8192][8][768] fp32
    const float* __restrict__ w,
    __half* __restrict__ s)
{
    __shared__ float ssim[M_ * D_];
    __shared__ float sw[H_ * M_];
    const int bn = blockIdx.x;
    const int tid = threadIdx.x;
    const float4* sg = (const float4*)(sim + (size_t)bn * M_ * D_);
    float4* sd = (float4*)ssim;
    for (int i = tid; i < M_ * D_ / 4; i += 256) sd[i] = sg[i];
    if (tid < H_ * M_) {
        int h = tid >> 3, m = tid & 7;
        sw[tid] = w[((size_t)h * (B_ * N_) + bn) * M_ + m];
    }
    __syncthreads();

    const float2* s2 = (const float2*)ssim;
    for (int idx = tid; idx < H_ * 384; idx += 256) {
        const int h = idx / 384, c2 = idx % 384;
        float ax = 0.f, ay = 0.f;
        #pragma unroll
        for (int m = 0; m < M_; m++) {
            float2 v = s2[m * 384 + c2];
            float wm_ = sw[h * M_ + m];
            ax += wm_ * v.x; ay += wm_ * v.y;
        }
        ((__half2*)s)[((size_t)h * (B_ * N_) + bn) * 384 + c2] =
            __floats2half2_rn(ax, ay);
    }
}

// ---------------- tensor-core flash attention (128 queries, 8 warps) ----------
#define SQV 72
#define QSZ (128 * SQV)
#define TSZ (64 * SQV)
#define ATTN_SMEM_MMA ((QSZ + 6 * TSZ) * 2)   // 73728 B

__global__ __launch_bounds__(256) void attn_mma_kernel(
    const __half* __restrict__ qkv,    // (B,N,2304): [q|k|v]
    const float*  __restrict__ bkv,
    const float*  __restrict__ ls,
    __half* __restrict__ outa,
    float* __restrict__ wg,
    float* __restrict__ asum)
{
    extern __shared__ __half smh[];
    __half* sQ = smh;
    __half* sK = sQ + QSZ;
    __half* sV = sK + 3 * TSZ;

    const int tid = threadIdx.x;
    const int warp = tid >> 5, lane = tid & 31;
    const int gid = lane >> 2, tig = lane & 3;
    const int n0 = blockIdx.x * 128, h = blockIdx.y, b = blockIdx.z;
    const int wq = warp * 16;
    const float scale = kSCALE;
    const int bn0 = b * N_ + n0;

    // Q load: 128 rows x 64 halves
    {
        const int row = tid >> 1, g0 = (tid & 1) << 5;
        const __half* src = qkv + (size_t)(bn0 + row) * QKVW + h * DH + g0;
        #pragma unroll
        for (int i = 0; i < 4; i++)
            cp16(&sQ[row * SQV + g0 + i * 8], src + i * 8);
    }
    auto load_tile = [&](int st, int kt) {
        const int row = tid >> 2, g = (tid & 3) << 4;
        size_t go = (size_t)(b * N_ + kt * 64 + row) * QKVW + D_ + h * DH + g;
        cp16(&sK[st * TSZ + row * SQV + g],     qkv + go);
        cp16(&sK[st * TSZ + row * SQV + g + 8], qkv + go + 8);
        cp16(&sV[st * TSZ + row * SQV + g],     qkv + go + D_);
        cp16(&sV[st * TSZ + row * SQV + g + 8], qkv + go + D_ + 8);
    };
    load_tile(0, 0); CP_COMMIT();
    load_tile(1, 1); CP_COMMIT();

    float m_[2] = {-1e30f, -1e30f}, l_[2] = {0.f, 0.f};
    float o[8][4];
    #pragma unroll
    for (int nt = 0; nt < 8; nt++)
        #pragma unroll
        for (int c = 0; c < 4; c++) o[nt][c] = 0.f;

    unsigned qa[4][4];
    const int a_off = (wq + (lane & 15)) * SQV + ((lane >> 4) << 3);
    const int kb_off = (((lane >> 4) << 3) + (lane & 7)) * SQV
                     + (((lane >> 3) & 1) << 3);
    const int vb_off = (((lane >> 3) & 1) * 8 + (lane & 7)) * SQV
                     + ((lane >> 4) << 3);
    bool qloaded = false;

    for (int kt = 0; kt < 8; kt++) {
        if (kt + 2 < 8) load_tile((kt + 2) % 3, kt + 2);
        CP_COMMIT();
        CP_WAIT2();
        __syncthreads();

        if (!qloaded) {
            #pragma unroll
            for (int ks = 0; ks < 4; ks++)
                ldm_x4(qa[ks], sQ + a_off + ks * 16);
            qloaded = true;
        }

        const __half* kb = sK + (kt % 3) * TSZ;
        const __half* vb = sV + (kt % 3) * TSZ;

        float sc[8][4];
        #pragma unroll
        for (int nt = 0; nt < 8; nt++)
            #pragma unroll
            for (int c = 0; c < 4; c++) sc[nt][c] = 0.f;
        #pragma unroll
        for (int ks = 0; ks < 4; ks++) {
            unsigned kf[4][4];
            #pragma unroll
            for (int ng = 0; ng < 4; ng++)
                ldm_x4(kf[ng], kb + kb_off + ng * 16 * SQV + ks * 16);
            #pragma unroll
            for (int nt = 0; nt < 8; nt++) {
                const unsigned* bp = kf[nt >> 1];
                const int e = (nt & 1) << 1;
                mma_f16(sc[nt], qa[ks][0], qa[ks][1], qa[ks][2], qa[ks][3],
                        bp[e], bp[e + 1]);
            }
        }
        #pragma unroll
        for (int nt = 0; nt < 8; nt++)
            #pragma unroll
            for (int c = 0; c < 4; c++) sc[nt][c] *= scale;

        #pragma unroll
        for (int s = 0; s < 2; s++) {
            const int e = s << 1;
            float tmax = -1e30f;
            #pragma unroll
            for (int nt = 0; nt < 8; nt++)
                tmax = fmaxf(tmax, fmaxf(sc[nt][e], sc[nt][e + 1]));
            tmax = fmaxf(tmax, __shfl_xor_sync(0xffffffffu, tmax, 1));
            tmax = fmaxf(tmax, __shfl_xor_sync(0xffffffffu, tmax, 2));
            float nm = fmaxf(m_[s], tmax);
            float corr = __expf(m_[s] - nm);
            float sum = 0.f;
            #pragma unroll
            for (int nt = 0; nt < 8; nt++) {
                sc[nt][e]     = __expf(sc[nt][e] - nm);
                sc[nt][e + 1] = __expf(sc[nt][e + 1] - nm);
                sum += sc[nt][e] + sc[nt][e + 1];
            }
            sum += __shfl_xor_sync(0xffffffffu, sum, 1);
            sum += __shfl_xor_sync(0xffffffffu, sum, 2);
            l_[s] = l_[s] * corr + sum;
            m_[s] = nm;
            #pragma unroll
            for (int nt = 0; nt < 8; nt++) {
                o[nt][e]     *= corr;
                o[nt][e + 1] *= corr;
            }
        }

        unsigned pa[4][4];
        #pragma unroll
        for (int kc = 0; kc < 4; kc++) {
            pa[kc][0] = packh2(sc[2 * kc][0],     sc[2 * kc][1]);
            pa[kc][1] = packh2(sc[2 * kc][2],     sc[2 * kc][3]);
            pa[kc][2] = packh2(sc[2 * kc + 1][0], sc[2 * kc + 1][1]);
            pa[kc][3] = packh2(sc[2 * kc + 1][2], sc[2 * kc + 1][3]);
        }

        #pragma unroll
        for (int kc = 0; kc < 4; kc++) {
            unsigned vf[4][4];
            #pragma unroll
            for (int ng = 0; ng < 4; ng++)
                ldm_x4t(vf[ng], vb + vb_off + kc * 16 * SQV + ng * 16);
            #pragma unroll
            for (int nt = 0; nt < 8; nt++) {
                const unsigned* bp = vf[nt >> 1];
                const int e = (nt & 1) << 1;
                mma_f16(o[nt], pa[kc][0], pa[kc][1], pa[kc][2], pa[kc][3],
                        bp[e], bp[e + 1]);
            }
        }
        __syncthreads();
    }

    // ---- sim logits + final normalize + writes ----
    #pragma unroll
    for (int s = 0; s < 2; s++) {
        const int rl = wq + gid + s * 8;
        const int e = s << 1;

        float qbk = 0.f;
        {
            const __half2* qp = (const __half2*)&sQ[rl * SQV + tig * 16];
            const float* bk = bkv + h * DH + tig * 16;
            #pragma unroll
            for (int j = 0; j < 8; j++) {
                float2 f = __half22float2(qp[j]);
                qbk += f.x * bk[2 * j] + f.y * bk[2 * j + 1];
            }
            qbk += __shfl_xor_sync(0xffffffffu, qbk, 1);
            qbk += __shfl_xor_sync(0xffffffffu, qbk, 2);
        }

        float2 raw = *(const float2*)&ls[(((size_t)b * H_ + h) * N_ + n0 + rl) * M_ + 2 * tig];
        float lg0 = scale * (raw.x + qbk);
        float lg1 = scale * (raw.y + qbk);

        float tmax = fmaxf(lg0, lg1);
        tmax = fmaxf(tmax, __shfl_xor_sync(0xffffffffu, tmax, 1));
        tmax = fmaxf(tmax, __shfl_xor_sync(0xffffffffu, tmax, 2));
        float nm = fmaxf(m_[s], tmax);
        float corr = __expf(m_[s] - nm);
        float p0 = __expf(lg0 - nm);
        float p1 = __expf(lg1 - nm);
        float ps = p0 + p1;
        ps += __shfl_xor_sync(0xffffffffu, ps, 1);
        ps += __shfl_xor_sync(0xffffffffu, ps, 2);
        float lnew = l_[s] * corr + ps;
        float inv = 1.f / lnew;

        size_t widx = (size_t)h * (B_ * N_) + bn0 + rl;
        float2 wout; wout.x = p0 * inv; wout.y = p1 * inv;
        *(float2*)&wg[widx * M_ + 2 * tig] = wout;
        if (tig == 0) asum[widx] = ps * inv;

        const float ci = corr * inv;
        __half2* op = (__half2*)&outa[(size_t)(bn0 + rl) * D_ + h * DH];
        #pragma unroll
        for (int nt = 0; nt < 8; nt++)
            op[nt * 4 + tig] = __floats2half2_rn(o[nt][e] * ci, o[nt][e + 1] * ci);
    }
}

// ---------------- launch ----------------
extern "C" void kernel_launch(void* const* d_in, const int* in_sizes, int n_in,
                              void* d_out, int out_size)
{
    const float* x   = (const float*)d_in[0];
    const float* sim = (const float*)d_in[1];
    const float* Wq  = (const float*)d_in[2];
    const float* bq  = (const float*)d_in[3];
    const float* Wkv = (const float*)d_in[4];
    const float* bkv = (const float*)d_in[5];
    const float* Wp  = (const float*)d_in[6];
    const float* bp  = (const float*)d_in[7];
    float* out = (float*)d_out;

    __half *qkv, *att, *xh, *tt, *ss, *wqkvt, *wkvh, *wpt;
    float  *ls, *wg, *asum, *zer, *bqkv;
    cudaGetSymbolAddress((void**)&qkv,   g_qkv);
    cudaGetSymbolAddress((void**)&att,   g_att);
    cudaGetSymbolAddress((void**)&xh,    g_xh);
    cudaGetSymbolAddress((void**)&tt,    g_t);
    cudaGetSymbolAddress((void**)&ss,    g_s);
    cudaGetSymbolAddress((void**)&ls,    g_ls);
    cudaGetSymbolAddress((void**)&wg,    g_w);
    cudaGetSymbolAddress((void**)&asum,  g_asum);
    cudaGetSymbolAddress((void**)&wqkvt, g_wqkvt);
    cudaGetSymbolAddress((void**)&wkvh,  g_wkvh);
    cudaGetSymbolAddress((void**)&wpt,   g_wpt);
    cudaGetSymbolAddress((void**)&bqkv,  g_bqkv);
    cudaGetSymbolAddress((void**)&zer,   g_zeros);

    cudaFuncSetAttribute(attn_mma_kernel,
                         cudaFuncAttributeMaxDynamicSharedMemorySize, ATTN_SMEM_MMA);
    cudaFuncSetAttribute(hgemm_bias<float>,
                         cudaFuncAttributeMaxDynamicSharedMemorySize, GEMM_SMEM);
    cudaFuncSetAttribute(hgemm_bias<__half>,
                         cudaFuncAttributeMaxDynamicSharedMemorySize, GEMM_SMEM);
    cudaFuncSetAttribute(hgemm_svw,
                         cudaFuncAttributeMaxDynamicSharedMemorySize, SVW_SMEM);

    const int BN = B_ * N_;

    // 0: bias concat
    biascat_kernel<<<(QKVW + 255) / 256, 256>>>(bq, bkv, bqkv);
    // 1-3: weight transposes
    transpose_h_kernel<<<dim3(D_ / 32, D_ / 32), dim3(32, 8)>>>(Wq, wqkvt, D_, D_);
    transpose_h_kernel<<<dim3(2 * D_ / 32, D_ / 32), dim3(32, 8)>>>(
        Wkv, wqkvt + (size_t)D_ * D_, D_, 2 * D_);
    transpose_h_kernel<<<dim3(D_ / 32, D_ / 32), dim3(32, 8)>>>(Wp, wpt, D_, D_);
    // 4: x -> half
    f2h_kernel<<<(BN * D_ / 4 + 255) / 256, 256>>>(x, xh, BN * D_ / 4);
    // 5: merged QKV projection  (ncu -s 5 captures this)
    hgemm_bias<__half><<<dim3(QKVW / 128, BN / 256), 256, GEMM_SMEM>>>(
        xh, D_, 0, wqkvt, D_, 0, bqkv, qkv, QKVW, 0, D_);
    // 6: Wkv row-major half (for t-GEMM)
    f2h_kernel<<<(D_ * 2 * D_ / 4 + 255) / 256, 256>>>(Wkv, wkvh, D_ * 2 * D_ / 4);
    // 7: t_h = q_h @ Wk_h^T (batched over heads)
    hgemm_bias<__half><<<dim3(D_ / 128, BN / 256, H_), 256, GEMM_SMEM>>>(
        qkv, QKVW, DH, wkvh, 2 * D_, DH, zer, tt, H_ * D_, D_, DH);
    // 8: raw sim logits (fp32 sim)
    logits_sim_kernel<<<BN, 256>>>(sim, tt, ls);
    // 9: flash attention
    attn_mma_kernel<<<dim3(N_ / 128, H_, B_), 256, ATTN_SMEM_MMA>>>(
        qkv, bkv, ls, att, wg, asum);
    // 10: s-pass
    spass_kernel<<<BN, 256>>>(sim, wg, ss);
    // 11: att += s_h @ Wv_h + asum*bv_h
    hgemm_svw<<<dim3(1, BN / 256, H_), 256, SVW_SMEM>>>(
        ss, wqkvt + (size_t)D_ * D_, bkv, asum, att);
    // 12: final projection
    hgemm_bias<float><<<dim3(D_ / 128, BN / 256), 256, GEMM_SMEM>>>(
        att, D_, 0, wpt, D_, 0, bp, out, D_, 0, D_);
}